// round 14
// baseline (speedup 1.0000x reference)
#include <cuda_runtime.h>
#include <math.h>
#include <float.h>
#include <stdint.h>

#define B_   64
#define T_   32
#define P_   64
#define E_   512
#define H_   512
#define V_   30000
#define IN_  1568
#define G4   2048      // 4*H
#define STAT 1056      // time-invariant prefix of x
#define NS   3         // side-chain buffer slots (one per lane: stream0, s1, s2)

// ---------------- scratch (static device memory) ----------------
__device__ __align__(16) float g_image_mean[B_*E_];
__device__ __align__(16) float g_x_static[B_*STAT];
__device__ __align__(16) float g_v[B_*P_*H_];
__device__ __align__(16) float g_hall[(T_+1)*B_*H_];   // h(0..T)
__device__ __align__(16) float g_m[2][B_*H_];
__device__ __align__(16) float g_gates_static[B_*G4];
__device__ __align__(16) float g_emb[T_*B_*E_];
__device__ __align__(16) float g_ge[T_*B_*G4];
__device__ __align__(16) float g_gates[B_*G4];
__device__ __align__(16) float g_hs[NS][B_*1024];
__device__ __align__(16) float g_hhs[NS][B_*1024];
__device__ __align__(16) float g_z[NS][B_*65];
__device__ __align__(16) float g_chh[NS][B_*E_];
__device__ __align__(16) float g_logits[NS][B_*V_];
__device__ __align__(16) float g_Wc[1024*E_];
__device__ __align__(16) float g_bc[1024];
__device__ __align__(16) float g_bihh[G4];
__device__ __align__(16) float g_maxlp[T_*B_];

// ---------------- tf32 mma helpers ----------------
__device__ __forceinline__ unsigned cvt_tf32(float x) {
    unsigned u; asm("cvt.rna.tf32.f32 %0, %1;" : "=r"(u) : "f"(x)); return u;
}
__device__ __forceinline__ void mma8(float* c, unsigned a0, unsigned a1, unsigned a2, unsigned a3,
                                     unsigned b0, unsigned b1) {
    asm volatile("mma.sync.aligned.m16n8k8.row.col.f32.tf32.tf32.f32 "
                 "{%0,%1,%2,%3}, {%4,%5,%6,%7}, {%8,%9}, {%0,%1,%2,%3};"
                 : "+f"(c[0]), "+f"(c[1]), "+f"(c[2]), "+f"(c[3])
                 : "r"(a0), "r"(a1), "r"(a2), "r"(a3), "r"(b0), "r"(b1));
}
__device__ __forceinline__ float tanh_acc(float x) {
    float xc = fminf(fmaxf(x, -10.f), 10.f);
    float e = __expf(2.f * xc);
    return __fdividef(e - 1.f, e + 1.f);
}

// C(MxN) = A(MxK) @ W(NxK)^T + bias + addend[(m%amod)*addN + n]  (single-pass TF32)
// Block tile 64(M) x 128(N), 256 threads = 8 warps as 4(M) x 2(N).
__global__ __launch_bounds__(256)
void mma_tf32(const float* __restrict__ A, int lda,
              const float* __restrict__ W, int ldw,
              const float* __restrict__ bias,
              const float* __restrict__ addend, int amod, int addN,
              float* __restrict__ C, int ldc, int M, int N, int K)
{
    __shared__ float As[64][42];
    __shared__ float Bs[128][42];
    const int tid = threadIdx.x;
    const int m0 = blockIdx.y * 64, n0 = blockIdx.x * 128;
    const int warp = tid >> 5, lane = tid & 31;
    const int wm = warp & 3, wn = warp >> 2;
    const int g = lane >> 2, t = lane & 3;

    float c[8][4];
#pragma unroll
    for (int i = 0; i < 8; i++)
#pragma unroll
        for (int j = 0; j < 4; j++) c[i][j] = 0.f;

    for (int kc = 0; kc < K; kc += 32) {
#pragma unroll
        for (int ii = 0; ii < 2; ii++) {
            int i = tid + ii * 256;
            int r = i >> 3, c4 = (i & 7) * 4;
            int sb = (c4 & 24) + ((c4 & 4) ? 1 : 0);
            float4 va = *(const float4*)(A + (size_t)(m0 + r) * lda + kc + c4);
            As[r][sb+0] = __uint_as_float(cvt_tf32(va.x));
            As[r][sb+2] = __uint_as_float(cvt_tf32(va.y));
            As[r][sb+4] = __uint_as_float(cvt_tf32(va.z));
            As[r][sb+6] = __uint_as_float(cvt_tf32(va.w));
        }
#pragma unroll
        for (int ii = 0; ii < 4; ii++) {
            int i = tid + ii * 256;
            int r = i >> 3, c4 = (i & 7) * 4;
            int sb = (c4 & 24) + ((c4 & 4) ? 1 : 0);
            int nrow = n0 + r;
            float4 vb = (nrow < N) ? *(const float4*)(W + (size_t)nrow * ldw + kc + c4)
                                   : make_float4(0.f, 0.f, 0.f, 0.f);
            Bs[r][sb+0] = __uint_as_float(cvt_tf32(vb.x));
            Bs[r][sb+2] = __uint_as_float(cvt_tf32(vb.y));
            Bs[r][sb+4] = __uint_as_float(cvt_tf32(vb.z));
            Bs[r][sb+6] = __uint_as_float(cvt_tf32(vb.w));
        }
        __syncthreads();
#pragma unroll
        for (int j = 0; j < 4; j++) {
            const int ra = wm*16 + g, ca = j*8 + 2*t;
            float2 aLo = *(const float2*)&As[ra][ca];
            float2 aHi = *(const float2*)&As[ra + 8][ca];
            unsigned a0 = __float_as_uint(aLo.x), a1 = __float_as_uint(aHi.x);
            unsigned a2 = __float_as_uint(aLo.y), a3 = __float_as_uint(aHi.y);
#pragma unroll
            for (int nt = 0; nt < 8; nt++) {
                float2 bb = *(const float2*)&Bs[wn*64 + nt*8 + g][ca];
                mma8(c[nt], a0, a1, a2, a3, __float_as_uint(bb.x), __float_as_uint(bb.y));
            }
        }
        __syncthreads();
    }

    const int rm0 = m0 + wm*16 + g, rm1 = rm0 + 8;
#pragma unroll
    for (int nt = 0; nt < 8; nt++) {
        int cn = n0 + wn*64 + nt*8 + 2*t;
#pragma unroll
        for (int q = 0; q < 2; q++) {
            int n = cn + q;
            if (n >= N) continue;
            float bv = bias ? bias[n] : 0.f;
            float x0 = c[nt][q] + bv;
            float x1 = c[nt][2+q] + bv;
            if (addend) {
                x0 += addend[(size_t)(rm0 % amod) * addN + n];
                x1 += addend[(size_t)(rm1 % amod) * addN + n];
            }
            C[(size_t)rm0 * ldc + n] = x0;
            C[(size_t)rm1 * ldc + n] = x1;
        }
    }
}

// ---------------- fp32 32x32-tile GEMM ----------------
__global__ __launch_bounds__(256)
void gemm32k(const float* __restrict__ A, int lda,
             const float* __restrict__ W, int ldw,
             const float* __restrict__ bias,
             const float* __restrict__ addend, int addmod,
             float* __restrict__ C, int ldc,
             int M, int N, int K, int act,
             int asplit_n, int asplit_off)
{
    __shared__ float As[32][36];
    __shared__ float Ws[32][36];
    const int bn0 = blockIdx.x * 32;
    const int bm0 = blockIdx.y * 32;
    if (asplit_off && bn0 >= asplit_n) A += asplit_off;
    const int tid = threadIdx.x;
    const int tx = tid & 15, ty = tid >> 4;
    const int lr = tid >> 3;
    const int lq = (tid & 7) * 4;
    float acc00=0.f, acc01=0.f, acc10=0.f, acc11=0.f;

    const int am = bm0 + lr;
    const int wn = bn0 + lr;
    const float* Ap = A + (size_t)am * lda + lq;
    const float* Wp = W + (size_t)wn * ldw + lq;

    for (int k0 = 0; k0 < K; k0 += 32) {
        float4 va = (am < M) ? __ldg((const float4*)(Ap + k0)) : make_float4(0.f,0.f,0.f,0.f);
        float4 vw = (wn < N) ? __ldg((const float4*)(Wp + k0)) : make_float4(0.f,0.f,0.f,0.f);
        As[lq+0][lr] = va.x; As[lq+1][lr] = va.y; As[lq+2][lr] = va.z; As[lq+3][lr] = va.w;
        Ws[lq+0][lr] = vw.x; Ws[lq+1][lr] = vw.y; Ws[lq+2][lr] = vw.z; Ws[lq+3][lr] = vw.w;
        __syncthreads();
#pragma unroll
        for (int k = 0; k < 32; k++) {
            float2 a2 = *(const float2*)&As[k][ty*2];
            float2 b2 = *(const float2*)&Ws[k][tx*2];
            acc00 += a2.x * b2.x; acc01 += a2.x * b2.y;
            acc10 += a2.y * b2.x; acc11 += a2.y * b2.y;
        }
        __syncthreads();
    }
    float accs[2][2] = {{acc00, acc01},{acc10, acc11}};
#pragma unroll
    for (int i = 0; i < 2; i++) {
        int m = bm0 + ty*2 + i;
        if (m >= M) continue;
#pragma unroll
        for (int j = 0; j < 2; j++) {
            int n = bn0 + tx*2 + j;
            if (n >= N) continue;
            float x = accs[i][j];
            if (bias)   x += bias[n];
            if (addend) x += addend[(size_t)(addmod ? (m % addmod) : m) * N + n];
            if (act == 1)      x = fmaxf(x, 0.f);
            else if (act == 2) x = tanhf(x);
            C[(size_t)m * ldc + n] = x;
        }
    }
}

// ---------------- small kernels ----------------
__global__ void k_imean(const float* __restrict__ image)
{
    int i = blockIdx.x * blockDim.x + threadIdx.x;
    if (i >= B_*E_) return;
    int b = i >> 9, e = i & 511;
    const float* p = image + (size_t)b * P_ * E_ + e;
    float s = 0.f;
#pragma unroll 8
    for (int pp = 0; pp < P_; pp++) s += p[(size_t)pp * E_];
    g_image_mean[i] = s * (1.f / P_);
}

__global__ void k_xstatic(const float* __restrict__ vp, const float* __restrict__ lab,
                          const float* __restrict__ topic)
{
    int i = blockIdx.x * blockDim.x + threadIdx.x;
    if (i >= B_*STAT) return;
    int b = i / STAT, c = i % STAT;
    float val;
    if (c < 512)        val = g_image_mean[b*512 + c];
    else if (c < 528)   val = vp[b*16 + c - 512];
    else if (c < 544)   val = lab[b*16 + c - 528];
    else                val = topic[b*512 + c - 544];
    g_x_static[i] = val;
}

__global__ void k_prep(const float* __restrict__ fhh_w, const float* __restrict__ fhh_b,
                       const float* __restrict__ fs_w,  const float* __restrict__ fs_b,
                       const float* __restrict__ bih,   const float* __restrict__ bhh)
{
    int i = blockIdx.x * blockDim.x + threadIdx.x;
    if (i < 1024*512)
        g_Wc[i] = (i < 512*512) ? fhh_w[i] : fs_w[i - 512*512];
    if (i < 1024)
        g_bc[i] = (i < 512) ? fhh_b[i] : fs_b[i - 512];
    if (i < 2048)
        g_bihh[i] = bih[i] + bhh[i];
}

__global__ void k_emb(const int* __restrict__ text, const float* __restrict__ wemb)
{
    int i = blockIdx.x * blockDim.x + threadIdx.x;
    if (i >= T_*B_*E_) return;
    int e = i & 511;
    int r = i >> 9;
    int b = r & 63, t = r >> 6;
    int tok = (t == 0) ? 0 : text[b*T_ + (t-1)];
    g_emb[i] = wemb[(size_t)tok * E_ + e];
}

// LSTM pointwise
__global__ void k_lstm(int t)
{
    int i = blockIdx.x * blockDim.x + threadIdx.x;
    if (i >= B_*H_) return;
    int b = i >> 9, h = i & 511;
    const float* g = g_gates + (size_t)b * G4;
    float ig = 1.f / (1.f + expf(-g[h]));
    float fg = 1.f / (1.f + expf(-g[h + 512]));
    float gg = tanhf(g[h + 1024]);
    float og = 1.f / (1.f + expf(-g[h + 1536]));
    float mn = fg * g_m[t & 1][i] + ig * gg;
    float hn = og * tanhf(mn);
    g_m[(t + 1) & 1][i] = mn;
    g_hall[(size_t)(t + 1) * B_ * H_ + i] = hn;
}

// z: grid (9, B); one attention position per warp
__global__ __launch_bounds__(256)
void k_attnz(const float* __restrict__ fz_w, const float* __restrict__ fz_b, int slot)
{
    int sl = blockIdx.x, b = blockIdx.y;
    __shared__ float hhsm[512];
    __shared__ float wz[512];
    int tid = threadIdx.x;
    const float* hhs = g_hhs[slot];
    for (int h = tid; h < 512; h += 256) { hhsm[h] = hhs[b*1024 + h]; wz[h] = fz_w[h]; }
    __syncthreads();
    int warp = tid >> 5, lane = tid & 31;
    int p = sl * 8 + warp;
    if (p > 64) return;
    const float* src = (p < 64) ? (g_v + ((size_t)b*64 + p) * 512)
                                : (hhs + b*1024 + 512);
    float s = 0.f;
    for (int h = lane; h < 512; h += 32) s += tanh_acc(src[h] + hhsm[h]) * wz[h];
#pragma unroll
    for (int o = 16; o; o >>= 1) s += __shfl_xor_sync(0xffffffffu, s, o);
    if (!lane) g_z[slot][b*65 + p] = s + fz_b[0];
}

// softmax(z) over all 65 slots -> attn output; context; chh = c + hh
__global__ __launch_bounds__(256)
void k_attnc(const float* __restrict__ image, float* __restrict__ out_attn, int t, int slot)
{
    int b = blockIdx.x;
    __shared__ float as_[65];
    int tid = threadIdx.x;
    int warp = tid >> 5, lane = tid & 31;
    const float* zrow = g_z[slot] + b*65;
    if (warp == 0) {
        float z0 = zrow[lane];
        float z1 = (lane + 32 < 64) ? zrow[lane + 32] : -FLT_MAX;
        float z2 = (lane == 0) ? zrow[64] : -FLT_MAX;
        float mx = fmaxf(fmaxf(z0, z1), z2);
#pragma unroll
        for (int o = 16; o; o >>= 1) mx = fmaxf(mx, __shfl_xor_sync(0xffffffffu, mx, o));
        float e0 = expf(z0 - mx);
        float e1 = (lane + 32 < 64) ? expf(z1 - mx) : 0.f;
        float e2 = (lane == 0) ? expf(z2 - mx) : 0.f;
        float se = e0 + e1 + e2;
#pragma unroll
        for (int o = 16; o; o >>= 1) se += __shfl_xor_sync(0xffffffffu, se, o);
        float inv = 1.f / se;
        float* oat = out_attn + ((size_t)b*T_ + t)*65;
        as_[lane] = e0 * inv;  oat[lane] = e0 * inv;
        if (lane + 32 < 64) { as_[lane+32] = e1 * inv; oat[lane+32] = e1 * inv; }
        if (lane == 0)      { as_[64]     = e2 * inv; oat[64]      = e2 * inv; }
    }
    __syncthreads();
    const float* srow = g_hs[slot] + b*1024 + 512;
    const float* hh   = g_hs[slot] + b*1024;
    float* chh = g_chh[slot] + b*512;
    for (int e = tid; e < 512; e += 256) {
        float c = as_[64] * srow[e];
        const float* im = image + (size_t)b * P_ * E_ + e;
#pragma unroll 8
        for (int p = 0; p < 64; p++) c += as_[p] * im[(size_t)p * E_];
        chh[e] = c + hh[e];
    }
}

// FUSED log-softmax: one block per batch, 1024 threads, two in-kernel passes.
__global__ __launch_bounds__(1024)
void k_lsm(const float* __restrict__ temp, float* __restrict__ out0, int t, int slot)
{
    int b = blockIdx.x, tid = threadIdx.x;
    int warp = tid >> 5, lane = tid & 31;
    __shared__ float rm[32], rs[32];
    __shared__ float bM, bS;
    const float it = 1.f / temp[b];
    const float4* x4 = (const float4*)(g_logits[slot] + (size_t)b * V_);

    float m = -FLT_MAX, s = 0.f;
    for (int i = tid; i < 7500; i += 1024) {
        float4 v = x4[i];
        float a = v.x*it, bb = v.y*it, cc = v.z*it, d = v.w*it;
        m = fmaxf(fmaxf(m, fmaxf(a, bb)), fmaxf(cc, d));
        s += __expf(a) + __expf(bb) + __expf(cc) + __expf(d);
    }
#pragma unroll
    for (int o = 16; o; o >>= 1) {
        m = fmaxf(m, __shfl_xor_sync(0xffffffffu, m, o));
        s += __shfl_xor_sync(0xffffffffu, s, o);
    }
    if (!lane) { rm[warp] = m; rs[warp] = s; }
    __syncthreads();
    if (warp == 0) {
        float M2 = rm[lane], S2 = rs[lane];
#pragma unroll
        for (int o = 16; o; o >>= 1) {
            M2 = fmaxf(M2, __shfl_xor_sync(0xffffffffu, M2, o));
            S2 += __shfl_xor_sync(0xffffffffu, S2, o);
        }
        if (!lane) { bM = M2; bS = S2; }
    }
    __syncthreads();
    float logS = __logf(bS);
    float4* o4 = (float4*)(out0 + ((size_t)b*T_ + t)*V_);
    for (int i = tid; i < 7500; i += 1024) {
        float4 v = x4[i];
        o4[i] = make_float4(v.x*it - logS, v.y*it - logS, v.z*it - logS, v.w*it - logS);
    }
    if (tid == 0) g_maxlp[t*64 + b] = bM - logS;
}

__global__ void k_final(float* __restrict__ out2)
{
    int b = threadIdx.x;
    if (b >= B_) return;
    float s = 0.f;
    for (int t = 0; t < T_; t++) s += g_maxlp[t*64 + b];
    out2[b] = s;
}

// ---------------- host ----------------
struct SideArgs {
    const float* image; const float* temp;
    const float* fc_w; const float* fc_b;
    const float* fc_z_w; const float* fc_z_b;
    const float* fc_p_w; const float* fc_p_b;
    float *hallp, *hsp, *hhsp, *chhp, *logitsp, *Wcp, *bcp;
    float *out0, *out1;
};

static void launch_side(cudaStream_t ss, int t, int slot, const SideArgs& a)
{
    gemm32k<<<dim3(1024/32, 2), 256, 0, ss>>>(a.hallp + (size_t)(t+1)*B_*H_, H_, a.fc_w, H_,
                                              a.fc_b, nullptr, 0,
                                              a.hsp + (size_t)slot*B_*1024, 1024,
                                              B_, 1024, H_, 1, 0, 0);
    gemm32k<<<dim3(1024/32, 2), 256, 0, ss>>>(a.hsp + (size_t)slot*B_*1024, 1024, a.Wcp, H_,
                                              a.bcp, nullptr, 0,
                                              a.hhsp + (size_t)slot*B_*1024, 1024,
                                              B_, 1024, H_, 0, 512, 512);
    k_attnz<<<dim3(9, B_), 256, 0, ss>>>(a.fc_z_w, a.fc_z_b, slot);
    k_attnc<<<B_, 256, 0, ss>>>(a.image, a.out1, t, slot);
    mma_tf32<<<dim3((V_ + 127)/128, 1), 256, 0, ss>>>(a.chhp + (size_t)slot*B_*E_, E_,
                                                      a.fc_p_w, E_, a.fc_p_b, nullptr, 1, 0,
                                                      a.logitsp + (size_t)slot*B_*V_, V_,
                                                      B_, V_, E_);
    k_lsm<<<B_, 1024, 0, ss>>>(a.temp, a.out0, t, slot);
}

extern "C" void kernel_launch(void* const* d_in, const int* in_sizes, int n_in,
                              void* d_out, int out_size)
{
    bool dictOrder = (in_sizes[5] == B_*T_);
    int o = dictOrder ? 1 : 0;
    const float* image    = (const float*)d_in[0];
    const float* vp       = (const float*)d_in[1];
    const float* label    = (const float*)d_in[2];
    const float* topic    = (const float*)d_in[3];
    const float* temp     = (const float*)d_in[4];
    const int*   text     = (const int*)(dictOrder ? d_in[5] : d_in[26]);
    const float* word_emb = (const float*)d_in[5+o];
    const float* fc_v_w   = (const float*)d_in[6+o];
    const float* fc_v_b   = (const float*)d_in[7+o];
    const float* fc_h_w   = (const float*)d_in[8+o];
    const float* fc_h_b   = (const float*)d_in[9+o];
    const float* fc_m_w   = (const float*)d_in[10+o];
    const float* fc_m_b   = (const float*)d_in[11+o];
    const float* w_ih     = (const float*)d_in[12+o];
    const float* w_hh     = (const float*)d_in[13+o];
    const float* b_ih     = (const float*)d_in[14+o];
    const float* b_hh     = (const float*)d_in[15+o];
    const float* fc_w     = (const float*)d_in[16+o];
    const float* fc_b     = (const float*)d_in[17+o];
    const float* fc_hh_w  = (const float*)d_in[18+o];
    const float* fc_hh_b  = (const float*)d_in[19+o];
    const float* fc_s_w   = (const float*)d_in[20+o];
    const float* fc_s_b   = (const float*)d_in[21+o];
    const float* fc_z_w   = (const float*)d_in[22+o];
    const float* fc_z_b   = (const float*)d_in[23+o];
    const float* fc_p_w   = (const float*)d_in[24+o];
    const float* fc_p_b   = (const float*)d_in[25+o];

    float *imean, *xstat, *vbuf, *hallp, *mbuf, *gstat, *embp, *gep, *gates,
          *hsp, *chhp, *logitsp, *Wcp, *bcp, *bihhp, *hhsp;
    cudaGetSymbolAddress((void**)&imean,   g_image_mean);
    cudaGetSymbolAddress((void**)&xstat,   g_x_static);
    cudaGetSymbolAddress((void**)&vbuf,    g_v);
    cudaGetSymbolAddress((void**)&hallp,   g_hall);
    cudaGetSymbolAddress((void**)&mbuf,    g_m);
    cudaGetSymbolAddress((void**)&gstat,   g_gates_static);
    cudaGetSymbolAddress((void**)&embp,    g_emb);
    cudaGetSymbolAddress((void**)&gep,     g_ge);
    cudaGetSymbolAddress((void**)&gates,   g_gates);
    cudaGetSymbolAddress((void**)&hsp,     g_hs);
    cudaGetSymbolAddress((void**)&chhp,    g_chh);
    cudaGetSymbolAddress((void**)&logitsp, g_logits);
    cudaGetSymbolAddress((void**)&Wcp,     g_Wc);
    cudaGetSymbolAddress((void**)&bcp,     g_bc);
    cudaGetSymbolAddress((void**)&bihhp,   g_bihh);
    cudaGetSymbolAddress((void**)&hhsp,    g_hhs);

    float* out0 = (float*)d_out;
    float* out1 = out0 + (size_t)B_*T_*V_;
    float* out2 = out1 + (size_t)B_*T_*65;

    // 3 streams total (proven leak-free in R13). Lane 0 = stream 0 (recurrence
    // first, then every 3rd side chain), lanes 1/2 = s1/s2.
    static cudaStream_t s1 = nullptr, s2 = nullptr;
    static cudaEvent_t evHs[T_] = {}, evD1 = nullptr, evD2 = nullptr;
    if (!s1) {
        cudaStreamCreateWithFlags(&s1, cudaStreamNonBlocking);
        cudaStreamCreateWithFlags(&s2, cudaStreamNonBlocking);
        for (int i = 0; i < T_; i++) cudaEventCreateWithFlags(&evHs[i], cudaEventDisableTiming);
        cudaEventCreateWithFlags(&evD1, cudaEventDisableTiming);
        cudaEventCreateWithFlags(&evD2, cudaEventDisableTiming);
    }

    SideArgs sa{image, temp, fc_w, fc_b, fc_z_w, fc_z_b, fc_p_w, fc_p_b,
                hallp, hsp, hhsp, chhp, logitsp, Wcp, bcp, out0, out1};

    // ---- prologue (stream 0) ----
    k_imean<<<(B_*E_ + 255)/256, 256>>>(image);
    k_xstatic<<<(B_*STAT + 255)/256, 256>>>(vp, label, topic);
    k_prep<<<(1024*512 + 255)/256, 256>>>(fc_hh_w, fc_hh_b, fc_s_w, fc_s_b, b_ih, b_hh);
    k_emb<<<(T_*B_*E_ + 255)/256, 256>>>(text, word_emb);

    mma_tf32<<<dim3(E_/128, (B_*P_)/64), 256>>>(image, E_, fc_v_w, E_, fc_v_b,
                                                nullptr, 1, 0, vbuf, H_, B_*P_, H_, E_);
    gemm32k<<<dim3(16, 2), 256>>>(imean, E_, fc_h_w, E_, fc_h_b, nullptr, 0,
                                  hallp, H_, B_, H_, E_, 2, 0, 0);
    gemm32k<<<dim3(16, 2), 256>>>(imean, E_, fc_m_w, E_, fc_m_b, nullptr, 0,
                                  mbuf, H_, B_, H_, E_, 2, 0, 0);
    gemm32k<<<dim3(G4/32, 2), 256>>>(xstat, STAT, w_ih, IN_, bihhp, nullptr, 0,
                                     gstat, G4, B_, G4, STAT, 0, 0, 0);
    mma_tf32<<<dim3(G4/128, (T_*B_)/64), 256>>>(embp, E_, w_ih + STAT, IN_, nullptr,
                                                gstat, 64, G4, gep, G4, T_*B_, G4, E_);

    // ---- phase 1: full recurrence on stream 0, per-step events ----
    for (int t = 0; t < T_; t++) {
        gemm32k<<<dim3(G4/32, 2), 256>>>(hallp + (size_t)t*B_*H_, H_, w_hh, H_,
                                         nullptr, gep + (size_t)t*B_*G4, 0,
                                         gates, G4, B_, G4, H_, 0, 0, 0);
        k_lstm<<<(B_*H_ + 255)/256, 256>>>(t);
        cudaEventRecord(evHs[t], 0);
    }

    // ---- phase 2: side chains round-robin over {stream0, s1, s2} ----
    for (int t = 0; t < T_; t++) {
        int slot = t % 3;
        cudaStream_t lane = (slot == 0) ? (cudaStream_t)0 : (slot == 1 ? s1 : s2);
        if (slot != 0) cudaStreamWaitEvent(lane, evHs[t], 0);
        // (stream-0 chains are ordered after the recurrence implicitly)
        launch_side(lane, t, slot, sa);
    }
    cudaEventRecord(evD1, s1);
    cudaEventRecord(evD2, s2);
    cudaStreamWaitEvent(0, evD1, 0);
    cudaStreamWaitEvent(0, evD2, 0);
    k_final<<<1, 64>>>(out2);
}

// round 15
// speedup vs baseline: 1.1596x; 1.1596x over previous
#include <cuda_runtime.h>
#include <math.h>
#include <float.h>
#include <stdint.h>

#define B_   64
#define T_   32
#define P_   64
#define E_   512
#define H_   512
#define V_   30000
#define IN_  1568
#define G4   2048      // 4*H
#define STAT 1056      // time-invariant prefix of x
#define NS   2         // side-chain buffer slots (one per side lane)

// ---------------- scratch (static device memory) ----------------
__device__ __align__(16) float g_image_mean[B_*E_];
__device__ __align__(16) float g_x_static[B_*STAT];
__device__ __align__(16) float g_v[B_*P_*H_];
__device__ __align__(16) float g_hall[(T_+1)*B_*H_];   // h(0..T)
__device__ __align__(16) float g_m[2][B_*H_];
__device__ __align__(16) float g_gates_static[B_*G4];
__device__ __align__(16) float g_emb[T_*B_*E_];
__device__ __align__(16) float g_ge[T_*B_*G4];
__device__ __align__(16) float g_gates[B_*G4];
__device__ __align__(16) float g_hs[NS][B_*1024];
__device__ __align__(16) float g_hhs[NS][B_*1024];
__device__ __align__(16) float g_chh[NS][B_*E_];
__device__ __align__(16) float g_logits[NS][B_*V_];
__device__ __align__(16) float g_Wc[1024*E_];
__device__ __align__(16) float g_bc[1024];
__device__ __align__(16) float g_bihh[G4];
__device__ __align__(16) float g_maxlp[T_*B_];

// ---------------- tf32 mma helpers ----------------
__device__ __forceinline__ unsigned cvt_tf32(float x) {
    unsigned u; asm("cvt.rna.tf32.f32 %0, %1;" : "=r"(u) : "f"(x)); return u;
}
__device__ __forceinline__ void mma8(float* c, unsigned a0, unsigned a1, unsigned a2, unsigned a3,
                                     unsigned b0, unsigned b1) {
    asm volatile("mma.sync.aligned.m16n8k8.row.col.f32.tf32.tf32.f32 "
                 "{%0,%1,%2,%3}, {%4,%5,%6,%7}, {%8,%9}, {%0,%1,%2,%3};"
                 : "+f"(c[0]), "+f"(c[1]), "+f"(c[2]), "+f"(c[3])
                 : "r"(a0), "r"(a1), "r"(a2), "r"(a3), "r"(b0), "r"(b1));
}
__device__ __forceinline__ float tanh_acc(float x) {
    float xc = fminf(fmaxf(x, -10.f), 10.f);
    float e = __expf(2.f * xc);
    return __fdividef(e - 1.f, e + 1.f);
}

// C(MxN) = A(MxK) @ W(NxK)^T + bias + addend[(m%amod)*addN + n]  (single-pass TF32)
// Block tile 64(M) x 128(N), 256 threads = 8 warps as 4(M) x 2(N).
__global__ __launch_bounds__(256)
void mma_tf32(const float* __restrict__ A, int lda,
              const float* __restrict__ W, int ldw,
              const float* __restrict__ bias,
              const float* __restrict__ addend, int amod, int addN,
              float* __restrict__ C, int ldc, int M, int N, int K)
{
    __shared__ float As[64][42];
    __shared__ float Bs[128][42];
    const int tid = threadIdx.x;
    const int m0 = blockIdx.y * 64, n0 = blockIdx.x * 128;
    const int warp = tid >> 5, lane = tid & 31;
    const int wm = warp & 3, wn = warp >> 2;
    const int g = lane >> 2, t = lane & 3;

    float c[8][4];
#pragma unroll
    for (int i = 0; i < 8; i++)
#pragma unroll
        for (int j = 0; j < 4; j++) c[i][j] = 0.f;

    for (int kc = 0; kc < K; kc += 32) {
#pragma unroll
        for (int ii = 0; ii < 2; ii++) {
            int i = tid + ii * 256;
            int r = i >> 3, c4 = (i & 7) * 4;
            int sb = (c4 & 24) + ((c4 & 4) ? 1 : 0);
            float4 va = *(const float4*)(A + (size_t)(m0 + r) * lda + kc + c4);
            As[r][sb+0] = __uint_as_float(cvt_tf32(va.x));
            As[r][sb+2] = __uint_as_float(cvt_tf32(va.y));
            As[r][sb+4] = __uint_as_float(cvt_tf32(va.z));
            As[r][sb+6] = __uint_as_float(cvt_tf32(va.w));
        }
#pragma unroll
        for (int ii = 0; ii < 4; ii++) {
            int i = tid + ii * 256;
            int r = i >> 3, c4 = (i & 7) * 4;
            int sb = (c4 & 24) + ((c4 & 4) ? 1 : 0);
            int nrow = n0 + r;
            float4 vb = (nrow < N) ? *(const float4*)(W + (size_t)nrow * ldw + kc + c4)
                                   : make_float4(0.f, 0.f, 0.f, 0.f);
            Bs[r][sb+0] = __uint_as_float(cvt_tf32(vb.x));
            Bs[r][sb+2] = __uint_as_float(cvt_tf32(vb.y));
            Bs[r][sb+4] = __uint_as_float(cvt_tf32(vb.z));
            Bs[r][sb+6] = __uint_as_float(cvt_tf32(vb.w));
        }
        __syncthreads();
#pragma unroll
        for (int j = 0; j < 4; j++) {
            const int ra = wm*16 + g, ca = j*8 + 2*t;
            float2 aLo = *(const float2*)&As[ra][ca];
            float2 aHi = *(const float2*)&As[ra + 8][ca];
            unsigned a0 = __float_as_uint(aLo.x), a1 = __float_as_uint(aHi.x);
            unsigned a2 = __float_as_uint(aLo.y), a3 = __float_as_uint(aHi.y);
#pragma unroll
            for (int nt = 0; nt < 8; nt++) {
                float2 bb = *(const float2*)&Bs[wn*64 + nt*8 + g][ca];
                mma8(c[nt], a0, a1, a2, a3, __float_as_uint(bb.x), __float_as_uint(bb.y));
            }
        }
        __syncthreads();
    }

    const int rm0 = m0 + wm*16 + g, rm1 = rm0 + 8;
#pragma unroll
    for (int nt = 0; nt < 8; nt++) {
        int cn = n0 + wn*64 + nt*8 + 2*t;
#pragma unroll
        for (int q = 0; q < 2; q++) {
            int n = cn + q;
            if (n >= N) continue;
            float bv = bias ? bias[n] : 0.f;
            float x0 = c[nt][q] + bv;
            float x1 = c[nt][2+q] + bv;
            if (addend) {
                x0 += addend[(size_t)(rm0 % amod) * addN + n];
                x1 += addend[(size_t)(rm1 % amod) * addN + n];
            }
            C[(size_t)rm0 * ldc + n] = x0;
            C[(size_t)rm1 * ldc + n] = x1;
        }
    }
}

// ---------------- fp32 32x32-tile GEMM ----------------
__global__ __launch_bounds__(256)
void gemm32k(const float* __restrict__ A, int lda,
             const float* __restrict__ W, int ldw,
             const float* __restrict__ bias,
             const float* __restrict__ addend, int addmod,
             float* __restrict__ C, int ldc,
             int M, int N, int K, int act,
             int asplit_n, int asplit_off)
{
    __shared__ float As[32][36];
    __shared__ float Ws[32][36];
    const int bn0 = blockIdx.x * 32;
    const int bm0 = blockIdx.y * 32;
    if (asplit_off && bn0 >= asplit_n) A += asplit_off;
    const int tid = threadIdx.x;
    const int tx = tid & 15, ty = tid >> 4;
    const int lr = tid >> 3;
    const int lq = (tid & 7) * 4;
    float acc00=0.f, acc01=0.f, acc10=0.f, acc11=0.f;

    const int am = bm0 + lr;
    const int wn = bn0 + lr;
    const float* Ap = A + (size_t)am * lda + lq;
    const float* Wp = W + (size_t)wn * ldw + lq;

    for (int k0 = 0; k0 < K; k0 += 32) {
        float4 va = (am < M) ? __ldg((const float4*)(Ap + k0)) : make_float4(0.f,0.f,0.f,0.f);
        float4 vw = (wn < N) ? __ldg((const float4*)(Wp + k0)) : make_float4(0.f,0.f,0.f,0.f);
        As[lq+0][lr] = va.x; As[lq+1][lr] = va.y; As[lq+2][lr] = va.z; As[lq+3][lr] = va.w;
        Ws[lq+0][lr] = vw.x; Ws[lq+1][lr] = vw.y; Ws[lq+2][lr] = vw.z; Ws[lq+3][lr] = vw.w;
        __syncthreads();
#pragma unroll
        for (int k = 0; k < 32; k++) {
            float2 a2 = *(const float2*)&As[k][ty*2];
            float2 b2 = *(const float2*)&Ws[k][tx*2];
            acc00 += a2.x * b2.x; acc01 += a2.x * b2.y;
            acc10 += a2.y * b2.x; acc11 += a2.y * b2.y;
        }
        __syncthreads();
    }
    float accs[2][2] = {{acc00, acc01},{acc10, acc11}};
#pragma unroll
    for (int i = 0; i < 2; i++) {
        int m = bm0 + ty*2 + i;
        if (m >= M) continue;
#pragma unroll
        for (int j = 0; j < 2; j++) {
            int n = bn0 + tx*2 + j;
            if (n >= N) continue;
            float x = accs[i][j];
            if (bias)   x += bias[n];
            if (addend) x += addend[(size_t)(addmod ? (m % addmod) : m) * N + n];
            if (act == 1)      x = fmaxf(x, 0.f);
            else if (act == 2) x = tanhf(x);
            C[(size_t)m * ldc + n] = x;
        }
    }
}

// ---------------- small kernels ----------------
__global__ void k_imean(const float* __restrict__ image)
{
    int i = blockIdx.x * blockDim.x + threadIdx.x;
    if (i >= B_*E_) return;
    int b = i >> 9, e = i & 511;
    const float* p = image + (size_t)b * P_ * E_ + e;
    float s = 0.f;
#pragma unroll 8
    for (int pp = 0; pp < P_; pp++) s += p[(size_t)pp * E_];
    g_image_mean[i] = s * (1.f / P_);
}

__global__ void k_xstatic(const float* __restrict__ vp, const float* __restrict__ lab,
                          const float* __restrict__ topic)
{
    int i = blockIdx.x * blockDim.x + threadIdx.x;
    if (i >= B_*STAT) return;
    int b = i / STAT, c = i % STAT;
    float val;
    if (c < 512)        val = g_image_mean[b*512 + c];
    else if (c < 528)   val = vp[b*16 + c - 512];
    else if (c < 544)   val = lab[b*16 + c - 528];
    else                val = topic[b*512 + c - 544];
    g_x_static[i] = val;
}

__global__ void k_prep(const float* __restrict__ fhh_w, const float* __restrict__ fhh_b,
                       const float* __restrict__ fs_w,  const float* __restrict__ fs_b,
                       const float* __restrict__ bih,   const float* __restrict__ bhh)
{
    int i = blockIdx.x * blockDim.x + threadIdx.x;
    if (i < 1024*512)
        g_Wc[i] = (i < 512*512) ? fhh_w[i] : fs_w[i - 512*512];
    if (i < 1024)
        g_bc[i] = (i < 512) ? fhh_b[i] : fs_b[i - 512];
    if (i < 2048)
        g_bihh[i] = bih[i] + bhh[i];
}

__global__ void k_emb(const int* __restrict__ text, const float* __restrict__ wemb)
{
    int i = blockIdx.x * blockDim.x + threadIdx.x;
    if (i >= T_*B_*E_) return;
    int e = i & 511;
    int r = i >> 9;
    int b = r & 63, t = r >> 6;
    int tok = (t == 0) ? 0 : text[b*T_ + (t-1)];
    g_emb[i] = wemb[(size_t)tok * E_ + e];
}

// LSTM pointwise
__global__ void k_lstm(int t)
{
    int i = blockIdx.x * blockDim.x + threadIdx.x;
    if (i >= B_*H_) return;
    int b = i >> 9, h = i & 511;
    const float* g = g_gates + (size_t)b * G4;
    float ig = 1.f / (1.f + expf(-g[h]));
    float fg = 1.f / (1.f + expf(-g[h + 512]));
    float gg = tanhf(g[h + 1024]);
    float og = 1.f / (1.f + expf(-g[h + 1536]));
    float mn = fg * g_m[t & 1][i] + ig * gg;
    float hn = og * tanhf(mn);
    g_m[(t + 1) & 1][i] = mn;
    g_hall[(size_t)(t + 1) * B_ * H_ + i] = hn;
}

// FUSED attention: z (65 dots with tanh) + softmax + context + chh, one block per batch.
__global__ __launch_bounds__(256)
void k_attn(const float* __restrict__ image,
            const float* __restrict__ fz_w, const float* __restrict__ fz_b,
            float* __restrict__ out_attn, int t, int slot)
{
    int b = blockIdx.x;
    __shared__ float hhsm[512];
    __shared__ float wz[512];
    __shared__ float zs[65];
    __shared__ float as_[65];
    int tid = threadIdx.x;
    int warp = tid >> 5, lane = tid & 31;
    const float* hhs = g_hhs[slot];
    for (int h = tid; h < 512; h += 256) { hhsm[h] = hhs[b*1024 + h]; wz[h] = fz_w[h]; }
    __syncthreads();
    // z
    for (int p = warp; p < 65; p += 8) {
        const float* src = (p < 64) ? (g_v + ((size_t)b*64 + p) * 512)
                                    : (hhs + b*1024 + 512);
        float s = 0.f;
        for (int h = lane; h < 512; h += 32) s += tanh_acc(src[h] + hhsm[h]) * wz[h];
#pragma unroll
        for (int o = 16; o; o >>= 1) s += __shfl_xor_sync(0xffffffffu, s, o);
        if (!lane) zs[p] = s + fz_b[0];
    }
    __syncthreads();
    // softmax over 65
    if (warp == 0) {
        float z0 = zs[lane];
        float z1 = (lane + 32 < 64) ? zs[lane + 32] : -FLT_MAX;
        float z2 = (lane == 0) ? zs[64] : -FLT_MAX;
        float mx = fmaxf(fmaxf(z0, z1), z2);
#pragma unroll
        for (int o = 16; o; o >>= 1) mx = fmaxf(mx, __shfl_xor_sync(0xffffffffu, mx, o));
        float e0 = expf(z0 - mx);
        float e1 = (lane + 32 < 64) ? expf(z1 - mx) : 0.f;
        float e2 = (lane == 0) ? expf(z2 - mx) : 0.f;
        float se = e0 + e1 + e2;
#pragma unroll
        for (int o = 16; o; o >>= 1) se += __shfl_xor_sync(0xffffffffu, se, o);
        float inv = 1.f / se;
        float* oat = out_attn + ((size_t)b*T_ + t)*65;
        as_[lane] = e0 * inv;  oat[lane] = e0 * inv;
        if (lane + 32 < 64) { as_[lane+32] = e1 * inv; oat[lane+32] = e1 * inv; }
        if (lane == 0)      { as_[64]     = e2 * inv; oat[64]      = e2 * inv; }
    }
    __syncthreads();
    // context + chh
    const float* srow = g_hs[slot] + b*1024 + 512;
    const float* hh   = g_hs[slot] + b*1024;
    float* chh = g_chh[slot] + b*512;
    for (int e = tid; e < 512; e += 256) {
        float c = as_[64] * srow[e];
        const float* im = image + (size_t)b * P_ * E_ + e;
#pragma unroll 8
        for (int p = 0; p < 64; p++) c += as_[p] * im[(size_t)p * E_];
        chh[e] = c + hh[e];
    }
}

// FUSED log-softmax: one block per batch, 1024 threads, two in-kernel passes.
__global__ __launch_bounds__(1024)
void k_lsm(const float* __restrict__ temp, float* __restrict__ out0, int t, int slot)
{
    int b = blockIdx.x, tid = threadIdx.x;
    int warp = tid >> 5, lane = tid & 31;
    __shared__ float rm[32], rs[32];
    __shared__ float bM, bS;
    const float it = 1.f / temp[b];
    const float4* x4 = (const float4*)(g_logits[slot] + (size_t)b * V_);

    float m = -FLT_MAX, s = 0.f;
    for (int i = tid; i < 7500; i += 1024) {
        float4 v = x4[i];
        float a = v.x*it, bb = v.y*it, cc = v.z*it, d = v.w*it;
        m = fmaxf(fmaxf(m, fmaxf(a, bb)), fmaxf(cc, d));
        s += __expf(a) + __expf(bb) + __expf(cc) + __expf(d);
    }
#pragma unroll
    for (int o = 16; o; o >>= 1) {
        m = fmaxf(m, __shfl_xor_sync(0xffffffffu, m, o));
        s += __shfl_xor_sync(0xffffffffu, s, o);
    }
    if (!lane) { rm[warp] = m; rs[warp] = s; }
    __syncthreads();
    if (warp == 0) {
        float M2 = rm[lane], S2 = rs[lane];
#pragma unroll
        for (int o = 16; o; o >>= 1) {
            M2 = fmaxf(M2, __shfl_xor_sync(0xffffffffu, M2, o));
            S2 += __shfl_xor_sync(0xffffffffu, S2, o);
        }
        if (!lane) { bM = M2; bS = S2; }
    }
    __syncthreads();
    float logS = __logf(bS);
    float4* o4 = (float4*)(out0 + ((size_t)b*T_ + t)*V_);
    for (int i = tid; i < 7500; i += 1024) {
        float4 v = x4[i];
        o4[i] = make_float4(v.x*it - logS, v.y*it - logS, v.z*it - logS, v.w*it - logS);
    }
    if (tid == 0) g_maxlp[t*64 + b] = bM - logS;
}

__global__ void k_final(float* __restrict__ out2)
{
    int b = threadIdx.x;
    if (b >= B_) return;
    float s = 0.f;
    for (int t = 0; t < T_; t++) s += g_maxlp[t*64 + b];
    out2[b] = s;
}

// ---------------- host ----------------
struct SideArgs {
    const float* image; const float* temp;
    const float* fc_w; const float* fc_b;
    const float* fc_z_w; const float* fc_z_b;
    const float* fc_p_w; const float* fc_p_b;
    float *hallp, *hsp, *hhsp, *chhp, *logitsp, *Wcp, *bcp;
    float *out0, *out1;
};

static void launch_side(cudaStream_t ss, int t, int slot, const SideArgs& a)
{
    gemm32k<<<dim3(1024/32, 2), 256, 0, ss>>>(a.hallp + (size_t)(t+1)*B_*H_, H_, a.fc_w, H_,
                                              a.fc_b, nullptr, 0,
                                              a.hsp + (size_t)slot*B_*1024, 1024,
                                              B_, 1024, H_, 1, 0, 0);
    gemm32k<<<dim3(1024/32, 2), 256, 0, ss>>>(a.hsp + (size_t)slot*B_*1024, 1024, a.Wcp, H_,
                                              a.bcp, nullptr, 0,
                                              a.hhsp + (size_t)slot*B_*1024, 1024,
                                              B_, 1024, H_, 0, 512, 512);
    k_attn<<<B_, 256, 0, ss>>>(a.image, a.fc_z_w, a.fc_z_b, a.out1, t, slot);
    mma_tf32<<<dim3((V_ + 127)/128, 1), 256, 0, ss>>>(a.chhp + (size_t)slot*B_*E_, E_,
                                                      a.fc_p_w, E_, a.fc_p_b, nullptr, 1, 0,
                                                      a.logitsp + (size_t)slot*B_*V_, V_,
                                                      B_, V_, E_);
    k_lsm<<<B_, 1024, 0, ss>>>(a.temp, a.out0, t, slot);
}

extern "C" void kernel_launch(void* const* d_in, const int* in_sizes, int n_in,
                              void* d_out, int out_size)
{
    bool dictOrder = (in_sizes[5] == B_*T_);
    int o = dictOrder ? 1 : 0;
    const float* image    = (const float*)d_in[0];
    const float* vp       = (const float*)d_in[1];
    const float* label    = (const float*)d_in[2];
    const float* topic    = (const float*)d_in[3];
    const float* temp     = (const float*)d_in[4];
    const int*   text     = (const int*)(dictOrder ? d_in[5] : d_in[26]);
    const float* word_emb = (const float*)d_in[5+o];
    const float* fc_v_w   = (const float*)d_in[6+o];
    const float* fc_v_b   = (const float*)d_in[7+o];
    const float* fc_h_w   = (const float*)d_in[8+o];
    const float* fc_h_b   = (const float*)d_in[9+o];
    const float* fc_m_w   = (const float*)d_in[10+o];
    const float* fc_m_b   = (const float*)d_in[11+o];
    const float* w_ih     = (const float*)d_in[12+o];
    const float* w_hh     = (const float*)d_in[13+o];
    const float* b_ih     = (const float*)d_in[14+o];
    const float* b_hh     = (const float*)d_in[15+o];
    const float* fc_w     = (const float*)d_in[16+o];
    const float* fc_b     = (const float*)d_in[17+o];
    const float* fc_hh_w  = (const float*)d_in[18+o];
    const float* fc_hh_b  = (const float*)d_in[19+o];
    const float* fc_s_w   = (const float*)d_in[20+o];
    const float* fc_s_b   = (const float*)d_in[21+o];
    const float* fc_z_w   = (const float*)d_in[22+o];
    const float* fc_z_b   = (const float*)d_in[23+o];
    const float* fc_p_w   = (const float*)d_in[24+o];
    const float* fc_p_b   = (const float*)d_in[25+o];

    float *imean, *xstat, *vbuf, *hallp, *mbuf, *gstat, *embp, *gep, *gates,
          *hsp, *chhp, *logitsp, *Wcp, *bcp, *bihhp, *hhsp;
    cudaGetSymbolAddress((void**)&imean,   g_image_mean);
    cudaGetSymbolAddress((void**)&xstat,   g_x_static);
    cudaGetSymbolAddress((void**)&vbuf,    g_v);
    cudaGetSymbolAddress((void**)&hallp,   g_hall);
    cudaGetSymbolAddress((void**)&mbuf,    g_m);
    cudaGetSymbolAddress((void**)&gstat,   g_gates_static);
    cudaGetSymbolAddress((void**)&embp,    g_emb);
    cudaGetSymbolAddress((void**)&gep,     g_ge);
    cudaGetSymbolAddress((void**)&gates,   g_gates);
    cudaGetSymbolAddress((void**)&hsp,     g_hs);
    cudaGetSymbolAddress((void**)&chhp,    g_chh);
    cudaGetSymbolAddress((void**)&logitsp, g_logits);
    cudaGetSymbolAddress((void**)&Wcp,     g_Wc);
    cudaGetSymbolAddress((void**)&bcp,     g_bc);
    cudaGetSymbolAddress((void**)&bihhp,   g_bihh);
    cudaGetSymbolAddress((void**)&hhsp,    g_hhs);

    float* out0 = (float*)d_out;
    float* out1 = out0 + (size_t)B_*T_*V_;
    float* out2 = out1 + (size_t)B_*T_*65;

    // 3 streams total (R13-proven leak-free). Stream 0 = recurrence only;
    // s1 = even-t chains (+ the prologue v GEMM), s2 = odd-t chains.
    static cudaStream_t s1 = nullptr, s2 = nullptr;
    static cudaEvent_t evH = nullptr, evV = nullptr, evD1 = nullptr, evD2 = nullptr;
    if (!s1) {
        cudaStreamCreateWithFlags(&s1, cudaStreamNonBlocking);
        cudaStreamCreateWithFlags(&s2, cudaStreamNonBlocking);
        cudaEventCreateWithFlags(&evH, cudaEventDisableTiming);
        cudaEventCreateWithFlags(&evV, cudaEventDisableTiming);
        cudaEventCreateWithFlags(&evD1, cudaEventDisableTiming);
        cudaEventCreateWithFlags(&evD2, cudaEventDisableTiming);
    }

    SideArgs sa{image, temp, fc_w, fc_b, fc_z_w, fc_z_b, fc_p_w, fc_p_b,
                hallp, hsp, hhsp, chhp, logitsp, Wcp, bcp, out0, out1};

    // ---- prologue: v GEMM on s1 (independent), rest on stream 0 ----
    mma_tf32<<<dim3(E_/128, (B_*P_)/64), 256, 0, s1>>>(image, E_, fc_v_w, E_, fc_v_b,
                                                       nullptr, 1, 0, vbuf, H_, B_*P_, H_, E_);
    cudaEventRecord(evV, s1);
    cudaStreamWaitEvent(s2, evV, 0);   // s2's chains also read g_v

    k_imean<<<(B_*E_ + 255)/256, 256>>>(image);
    k_xstatic<<<(B_*STAT + 255)/256, 256>>>(vp, label, topic);
    k_prep<<<(1024*512 + 255)/256, 256>>>(fc_hh_w, fc_hh_b, fc_s_w, fc_s_b, b_ih, b_hh);
    k_emb<<<(T_*B_*E_ + 255)/256, 256>>>(text, word_emb);
    gemm32k<<<dim3(16, 2), 256>>>(imean, E_, fc_h_w, E_, fc_h_b, nullptr, 0,
                                  hallp, H_, B_, H_, E_, 2, 0, 0);
    gemm32k<<<dim3(16, 2), 256>>>(imean, E_, fc_m_w, E_, fc_m_b, nullptr, 0,
                                  mbuf, H_, B_, H_, E_, 2, 0, 0);
    gemm32k<<<dim3(G4/32, 2), 256>>>(xstat, STAT, w_ih, IN_, bihhp, nullptr, 0,
                                     gstat, G4, B_, G4, STAT, 0, 0, 0);
    mma_tf32<<<dim3(G4/128, (T_*B_)/64), 256>>>(embp, E_, w_ih + STAT, IN_, nullptr,
                                                gstat, 64, G4, gep, G4, T_*B_, G4, E_);

    // ---- interleaved: stream 0 recurrence; s1/s2 side chains by parity (R13 schedule) ----
    for (int t = 0; t < T_; t++) {
        gemm32k<<<dim3(G4/32, 2), 256>>>(hallp + (size_t)t*B_*H_, H_, w_hh, H_,
                                         nullptr, gep + (size_t)t*B_*G4, 0,
                                         gates, G4, B_, G4, H_, 0, 0, 0);
        k_lstm<<<(B_*H_ + 255)/256, 256>>>(t);
        cudaEventRecord(evH, 0);

        int slot = t & 1;
        cudaStream_t lane = slot ? s2 : s1;
        cudaStreamWaitEvent(lane, evH, 0);
        launch_side(lane, t, slot, sa);
    }
    cudaEventRecord(evD1, s1);
    cudaEventRecord(evD2, s2);
    cudaStreamWaitEvent(0, evD1, 0);
    cudaStreamWaitEvent(0, evD2, 0);
    k_final<<<1, 64>>>(out2);
}

// round 16
// speedup vs baseline: 1.2853x; 1.1084x over previous
#include <cuda_runtime.h>
#include <math.h>
#include <float.h>
#include <stdint.h>

#define B_   64
#define T_   32
#define P_   64
#define E_   512
#define H_   512
#define V_   30000
#define IN_  1568
#define G4   2048      // 4*H
#define STAT 1056      // time-invariant prefix of x
#define NS   3         // side-chain buffer slots (one per side lane)

// ---------------- scratch (static device memory) ----------------
__device__ __align__(16) float g_image_mean[B_*E_];
__device__ __align__(16) float g_x_static[B_*STAT];
__device__ __align__(16) float g_v[B_*P_*H_];
__device__ __align__(16) float g_hall[(T_+1)*B_*H_];   // h(0..T)
__device__ __align__(16) float g_m[2][B_*H_];
__device__ __align__(16) float g_gates_static[B_*G4];
__device__ __align__(16) float g_emb[T_*B_*E_];
__device__ __align__(16) float g_ge[T_*B_*G4];
__device__ __align__(16) float g_gates[B_*G4];
__device__ __align__(16) float g_hs[NS][B_*1024];
__device__ __align__(16) float g_hhs[NS][B_*1024];
__device__ __align__(16) float g_chh[NS][B_*E_];
__device__ __align__(16) float g_logits[NS][B_*V_];
__device__ __align__(16) float g_wp[(size_t)V_*E_];    // fc_p_w pre-rounded to tf32 bits (61MB)
__device__ __align__(16) float g_Wc[1024*E_];
__device__ __align__(16) float g_bc[1024];
__device__ __align__(16) float g_bihh[G4];
__device__ __align__(16) float g_maxlp[T_*B_];

// ---------------- tf32 mma helpers ----------------
__device__ __forceinline__ unsigned cvt_tf32(float x) {
    unsigned u; asm("cvt.rna.tf32.f32 %0, %1;" : "=r"(u) : "f"(x)); return u;
}
__device__ __forceinline__ void mma8(float* c, unsigned a0, unsigned a1, unsigned a2, unsigned a3,
                                     unsigned b0, unsigned b1) {
    asm volatile("mma.sync.aligned.m16n8k8.row.col.f32.tf32.tf32.f32 "
                 "{%0,%1,%2,%3}, {%4,%5,%6,%7}, {%8,%9}, {%0,%1,%2,%3};"
                 : "+f"(c[0]), "+f"(c[1]), "+f"(c[2]), "+f"(c[3])
                 : "r"(a0), "r"(a1), "r"(a2), "r"(a3), "r"(b0), "r"(b1));
}
__device__ __forceinline__ float tanh_acc(float x) {
    float xc = fminf(fmaxf(x, -10.f), 10.f);
    float e = __expf(2.f * xc);
    return __fdividef(e - 1.f, e + 1.f);
}

// C(MxN) = A(MxK) @ W(NxK)^T + bias + addend[(m%amod)*addN + n]  (single-pass TF32)
// Block tile 64(M) x 128(N), 256 threads = 8 warps as 4(M) x 2(N).
// rawB != 0: W already holds tf32-rounded bits -> skip cvt on B staging.
__global__ __launch_bounds__(256)
void mma_tf32(const float* __restrict__ A, int lda,
              const float* __restrict__ W, int ldw,
              const float* __restrict__ bias,
              const float* __restrict__ addend, int amod, int addN,
              float* __restrict__ C, int ldc, int M, int N, int K, int rawB)
{
    __shared__ float As[64][42];
    __shared__ float Bs[128][42];
    const int tid = threadIdx.x;
    const int m0 = blockIdx.y * 64, n0 = blockIdx.x * 128;
    const int warp = tid >> 5, lane = tid & 31;
    const int wm = warp & 3, wn = warp >> 2;
    const int g = lane >> 2, t = lane & 3;

    float c[8][4];
#pragma unroll
    for (int i = 0; i < 8; i++)
#pragma unroll
        for (int j = 0; j < 4; j++) c[i][j] = 0.f;

    for (int kc = 0; kc < K; kc += 32) {
#pragma unroll
        for (int ii = 0; ii < 2; ii++) {
            int i = tid + ii * 256;
            int r = i >> 3, c4 = (i & 7) * 4;
            int sb = (c4 & 24) + ((c4 & 4) ? 1 : 0);
            float4 va = *(const float4*)(A + (size_t)(m0 + r) * lda + kc + c4);
            As[r][sb+0] = __uint_as_float(cvt_tf32(va.x));
            As[r][sb+2] = __uint_as_float(cvt_tf32(va.y));
            As[r][sb+4] = __uint_as_float(cvt_tf32(va.z));
            As[r][sb+6] = __uint_as_float(cvt_tf32(va.w));
        }
#pragma unroll
        for (int ii = 0; ii < 4; ii++) {
            int i = tid + ii * 256;
            int r = i >> 3, c4 = (i & 7) * 4;
            int sb = (c4 & 24) + ((c4 & 4) ? 1 : 0);
            int nrow = n0 + r;
            float4 vb = (nrow < N) ? *(const float4*)(W + (size_t)nrow * ldw + kc + c4)
                                   : make_float4(0.f, 0.f, 0.f, 0.f);
            if (rawB) {
                Bs[r][sb+0] = vb.x; Bs[r][sb+2] = vb.y;
                Bs[r][sb+4] = vb.z; Bs[r][sb+6] = vb.w;
            } else {
                Bs[r][sb+0] = __uint_as_float(cvt_tf32(vb.x));
                Bs[r][sb+2] = __uint_as_float(cvt_tf32(vb.y));
                Bs[r][sb+4] = __uint_as_float(cvt_tf32(vb.z));
                Bs[r][sb+6] = __uint_as_float(cvt_tf32(vb.w));
            }
        }
        __syncthreads();
#pragma unroll
        for (int j = 0; j < 4; j++) {
            const int ra = wm*16 + g, ca = j*8 + 2*t;
            float2 aLo = *(const float2*)&As[ra][ca];
            float2 aHi = *(const float2*)&As[ra + 8][ca];
            unsigned a0 = __float_as_uint(aLo.x), a1 = __float_as_uint(aHi.x);
            unsigned a2 = __float_as_uint(aLo.y), a3 = __float_as_uint(aHi.y);
#pragma unroll
            for (int nt = 0; nt < 8; nt++) {
                float2 bb = *(const float2*)&Bs[wn*64 + nt*8 + g][ca];
                mma8(c[nt], a0, a1, a2, a3, __float_as_uint(bb.x), __float_as_uint(bb.y));
            }
        }
        __syncthreads();
    }

    const int rm0 = m0 + wm*16 + g, rm1 = rm0 + 8;
#pragma unroll
    for (int nt = 0; nt < 8; nt++) {
        int cn = n0 + wn*64 + nt*8 + 2*t;
#pragma unroll
        for (int q = 0; q < 2; q++) {
            int n = cn + q;
            if (n >= N) continue;
            float bv = bias ? bias[n] : 0.f;
            float x0 = c[nt][q] + bv;
            float x1 = c[nt][2+q] + bv;
            if (addend) {
                x0 += addend[(size_t)(rm0 % amod) * addN + n];
                x1 += addend[(size_t)(rm1 % amod) * addN + n];
            }
            C[(size_t)rm0 * ldc + n] = x0;
            C[(size_t)rm1 * ldc + n] = x1;
        }
    }
}

// ---------------- fp32 32x32-tile GEMM ----------------
__global__ __launch_bounds__(256)
void gemm32k(const float* __restrict__ A, int lda,
             const float* __restrict__ W, int ldw,
             const float* __restrict__ bias,
             const float* __restrict__ addend, int addmod,
             float* __restrict__ C, int ldc,
             int M, int N, int K, int act,
             int asplit_n, int asplit_off)
{
    __shared__ float As[32][36];
    __shared__ float Ws[32][36];
    const int bn0 = blockIdx.x * 32;
    const int bm0 = blockIdx.y * 32;
    if (asplit_off && bn0 >= asplit_n) A += asplit_off;
    const int tid = threadIdx.x;
    const int tx = tid & 15, ty = tid >> 4;
    const int lr = tid >> 3;
    const int lq = (tid & 7) * 4;
    float acc00=0.f, acc01=0.f, acc10=0.f, acc11=0.f;

    const int am = bm0 + lr;
    const int wn = bn0 + lr;
    const float* Ap = A + (size_t)am * lda + lq;
    const float* Wp = W + (size_t)wn * ldw + lq;

    for (int k0 = 0; k0 < K; k0 += 32) {
        float4 va = (am < M) ? __ldg((const float4*)(Ap + k0)) : make_float4(0.f,0.f,0.f,0.f);
        float4 vw = (wn < N) ? __ldg((const float4*)(Wp + k0)) : make_float4(0.f,0.f,0.f,0.f);
        As[lq+0][lr] = va.x; As[lq+1][lr] = va.y; As[lq+2][lr] = va.z; As[lq+3][lr] = va.w;
        Ws[lq+0][lr] = vw.x; Ws[lq+1][lr] = vw.y; Ws[lq+2][lr] = vw.z; Ws[lq+3][lr] = vw.w;
        __syncthreads();
#pragma unroll
        for (int k = 0; k < 32; k++) {
            float2 a2 = *(const float2*)&As[k][ty*2];
            float2 b2 = *(const float2*)&Ws[k][tx*2];
            acc00 += a2.x * b2.x; acc01 += a2.x * b2.y;
            acc10 += a2.y * b2.x; acc11 += a2.y * b2.y;
        }
        __syncthreads();
    }
    float accs[2][2] = {{acc00, acc01},{acc10, acc11}};
#pragma unroll
    for (int i = 0; i < 2; i++) {
        int m = bm0 + ty*2 + i;
        if (m >= M) continue;
#pragma unroll
        for (int j = 0; j < 2; j++) {
            int n = bn0 + tx*2 + j;
            if (n >= N) continue;
            float x = accs[i][j];
            if (bias)   x += bias[n];
            if (addend) x += addend[(size_t)(addmod ? (m % addmod) : m) * N + n];
            if (act == 1)      x = fmaxf(x, 0.f);
            else if (act == 2) x = tanhf(x);
            C[(size_t)m * ldc + n] = x;
        }
    }
}

// ---------------- small kernels ----------------
__global__ void k_imean(const float* __restrict__ image)
{
    int i = blockIdx.x * blockDim.x + threadIdx.x;
    if (i >= B_*E_) return;
    int b = i >> 9, e = i & 511;
    const float* p = image + (size_t)b * P_ * E_ + e;
    float s = 0.f;
#pragma unroll 8
    for (int pp = 0; pp < P_; pp++) s += p[(size_t)pp * E_];
    g_image_mean[i] = s * (1.f / P_);
}

__global__ void k_xstatic(const float* __restrict__ vp, const float* __restrict__ lab,
                          const float* __restrict__ topic)
{
    int i = blockIdx.x * blockDim.x + threadIdx.x;
    if (i >= B_*STAT) return;
    int b = i / STAT, c = i % STAT;
    float val;
    if (c < 512)        val = g_image_mean[b*512 + c];
    else if (c < 528)   val = vp[b*16 + c - 512];
    else if (c < 544)   val = lab[b*16 + c - 528];
    else                val = topic[b*512 + c - 544];
    g_x_static[i] = val;
}

__global__ void k_prep(const float* __restrict__ fhh_w, const float* __restrict__ fhh_b,
                       const float* __restrict__ fs_w,  const float* __restrict__ fs_b,
                       const float* __restrict__ bih,   const float* __restrict__ bhh)
{
    int i = blockIdx.x * blockDim.x + threadIdx.x;
    if (i < 1024*512)
        g_Wc[i] = (i < 512*512) ? fhh_w[i] : fs_w[i - 512*512];
    if (i < 1024)
        g_bc[i] = (i < 512) ? fhh_b[i] : fs_b[i - 512];
    if (i < 2048)
        g_bihh[i] = bih[i] + bhh[i];
}

// pre-round fc_p_w to tf32 bits (vectorized)
__global__ void k_round(const float* __restrict__ w)
{
    size_t i = (size_t)(blockIdx.x * blockDim.x + threadIdx.x) * 4;
    if (i >= (size_t)V_*E_) return;
    float4 v = *(const float4*)(w + i);
    float4 r;
    r.x = __uint_as_float(cvt_tf32(v.x));
    r.y = __uint_as_float(cvt_tf32(v.y));
    r.z = __uint_as_float(cvt_tf32(v.z));
    r.w = __uint_as_float(cvt_tf32(v.w));
    *(float4*)(g_wp + i) = r;
}

__global__ void k_emb(const int* __restrict__ text, const float* __restrict__ wemb)
{
    int i = blockIdx.x * blockDim.x + threadIdx.x;
    if (i >= T_*B_*E_) return;
    int e = i & 511;
    int r = i >> 9;
    int b = r & 63, t = r >> 6;
    int tok = (t == 0) ? 0 : text[b*T_ + (t-1)];
    g_emb[i] = wemb[(size_t)tok * E_ + e];
}

// LSTM pointwise
__global__ void k_lstm(int t)
{
    int i = blockIdx.x * blockDim.x + threadIdx.x;
    if (i >= B_*H_) return;
    int b = i >> 9, h = i & 511;
    const float* g = g_gates + (size_t)b * G4;
    float ig = 1.f / (1.f + expf(-g[h]));
    float fg = 1.f / (1.f + expf(-g[h + 512]));
    float gg = tanhf(g[h + 1024]);
    float og = 1.f / (1.f + expf(-g[h + 1536]));
    float mn = fg * g_m[t & 1][i] + ig * gg;
    float hn = og * tanhf(mn);
    g_m[(t + 1) & 1][i] = mn;
    g_hall[(size_t)(t + 1) * B_ * H_ + i] = hn;
}

// FUSED attention: z + softmax + context + chh, one block per batch.
__global__ __launch_bounds__(256)
void k_attn(const float* __restrict__ image,
            const float* __restrict__ fz_w, const float* __restrict__ fz_b,
            float* __restrict__ out_attn, int t, int slot)
{
    int b = blockIdx.x;
    __shared__ float hhsm[512];
    __shared__ float wz[512];
    __shared__ float zs[65];
    __shared__ float as_[65];
    int tid = threadIdx.x;
    int warp = tid >> 5, lane = tid & 31;
    const float* hhs = g_hhs[slot];
    for (int h = tid; h < 512; h += 256) { hhsm[h] = hhs[b*1024 + h]; wz[h] = fz_w[h]; }
    __syncthreads();
    for (int p = warp; p < 65; p += 8) {
        const float* src = (p < 64) ? (g_v + ((size_t)b*64 + p) * 512)
                                    : (hhs + b*1024 + 512);
        float s = 0.f;
        for (int h = lane; h < 512; h += 32) s += tanh_acc(src[h] + hhsm[h]) * wz[h];
#pragma unroll
        for (int o = 16; o; o >>= 1) s += __shfl_xor_sync(0xffffffffu, s, o);
        if (!lane) zs[p] = s + fz_b[0];
    }
    __syncthreads();
    if (warp == 0) {
        float z0 = zs[lane];
        float z1 = (lane + 32 < 64) ? zs[lane + 32] : -FLT_MAX;
        float z2 = (lane == 0) ? zs[64] : -FLT_MAX;
        float mx = fmaxf(fmaxf(z0, z1), z2);
#pragma unroll
        for (int o = 16; o; o >>= 1) mx = fmaxf(mx, __shfl_xor_sync(0xffffffffu, mx, o));
        float e0 = expf(z0 - mx);
        float e1 = (lane + 32 < 64) ? expf(z1 - mx) : 0.f;
        float e2 = (lane == 0) ? expf(z2 - mx) : 0.f;
        float se = e0 + e1 + e2;
#pragma unroll
        for (int o = 16; o; o >>= 1) se += __shfl_xor_sync(0xffffffffu, se, o);
        float inv = 1.f / se;
        float* oat = out_attn + ((size_t)b*T_ + t)*65;
        as_[lane] = e0 * inv;  oat[lane] = e0 * inv;
        if (lane + 32 < 64) { as_[lane+32] = e1 * inv; oat[lane+32] = e1 * inv; }
        if (lane == 0)      { as_[64]     = e2 * inv; oat[64]      = e2 * inv; }
    }
    __syncthreads();
    const float* srow = g_hs[slot] + b*1024 + 512;
    const float* hh   = g_hs[slot] + b*1024;
    float* chh = g_chh[slot] + b*512;
    for (int e = tid; e < 512; e += 256) {
        float c = as_[64] * srow[e];
        const float* im = image + (size_t)b * P_ * E_ + e;
#pragma unroll 8
        for (int p = 0; p < 64; p++) c += as_[p] * im[(size_t)p * E_];
        chh[e] = c + hh[e];
    }
}

// FUSED log-softmax: one block per batch, 1024 threads, two in-kernel passes.
__global__ __launch_bounds__(1024)
void k_lsm(const float* __restrict__ temp, float* __restrict__ out0, int t, int slot)
{
    int b = blockIdx.x, tid = threadIdx.x;
    int warp = tid >> 5, lane = tid & 31;
    __shared__ float rm[32], rs[32];
    __shared__ float bM, bS;
    const float it = 1.f / temp[b];
    const float4* x4 = (const float4*)(g_logits[slot] + (size_t)b * V_);

    float m = -FLT_MAX, s = 0.f;
    for (int i = tid; i < 7500; i += 1024) {
        float4 v = x4[i];
        float a = v.x*it, bb = v.y*it, cc = v.z*it, d = v.w*it;
        m = fmaxf(fmaxf(m, fmaxf(a, bb)), fmaxf(cc, d));
        s += __expf(a) + __expf(bb) + __expf(cc) + __expf(d);
    }
#pragma unroll
    for (int o = 16; o; o >>= 1) {
        m = fmaxf(m, __shfl_xor_sync(0xffffffffu, m, o));
        s += __shfl_xor_sync(0xffffffffu, s, o);
    }
    if (!lane) { rm[warp] = m; rs[warp] = s; }
    __syncthreads();
    if (warp == 0) {
        float M2 = rm[lane], S2 = rs[lane];
#pragma unroll
        for (int o = 16; o; o >>= 1) {
            M2 = fmaxf(M2, __shfl_xor_sync(0xffffffffu, M2, o));
            S2 += __shfl_xor_sync(0xffffffffu, S2, o);
        }
        if (!lane) { bM = M2; bS = S2; }
    }
    __syncthreads();
    float logS = __logf(bS);
    float4* o4 = (float4*)(out0 + ((size_t)b*T_ + t)*V_);
    for (int i = tid; i < 7500; i += 1024) {
        float4 v = x4[i];
        o4[i] = make_float4(v.x*it - logS, v.y*it - logS, v.z*it - logS, v.w*it - logS);
    }
    if (tid == 0) g_maxlp[t*64 + b] = bM - logS;
}

__global__ void k_final(float* __restrict__ out2)
{
    int b = threadIdx.x;
    if (b >= B_) return;
    float s = 0.f;
    for (int t = 0; t < T_; t++) s += g_maxlp[t*64 + b];
    out2[b] = s;
}

// ---------------- host ----------------
struct SideArgs {
    const float* image; const float* temp;
    const float* fc_w; const float* fc_b;
    const float* fc_z_w; const float* fc_z_b;
    const float* fc_p_b;
    float *hallp, *hsp, *hhsp, *chhp, *logitsp, *Wcp, *bcp, *wpp;
    float *out0, *out1;
};

static void launch_side(cudaStream_t ss, int t, int slot, const SideArgs& a)
{
    gemm32k<<<dim3(1024/32, 2), 256, 0, ss>>>(a.hallp + (size_t)(t+1)*B_*H_, H_, a.fc_w, H_,
                                              a.fc_b, nullptr, 0,
                                              a.hsp + (size_t)slot*B_*1024, 1024,
                                              B_, 1024, H_, 1, 0, 0);
    gemm32k<<<dim3(1024/32, 2), 256, 0, ss>>>(a.hsp + (size_t)slot*B_*1024, 1024, a.Wcp, H_,
                                              a.bcp, nullptr, 0,
                                              a.hhsp + (size_t)slot*B_*1024, 1024,
                                              B_, 1024, H_, 0, 512, 512);
    k_attn<<<B_, 256, 0, ss>>>(a.image, a.fc_z_w, a.fc_z_b, a.out1, t, slot);
    mma_tf32<<<dim3((V_ + 127)/128, 1), 256, 0, ss>>>(a.chhp + (size_t)slot*B_*E_, E_,
                                                      a.wpp, E_, a.fc_p_b, nullptr, 1, 0,
                                                      a.logitsp + (size_t)slot*B_*V_, V_,
                                                      B_, V_, E_, 1 /*rawB*/);
    k_lsm<<<B_, 1024, 0, ss>>>(a.temp, a.out0, t, slot);
}

extern "C" void kernel_launch(void* const* d_in, const int* in_sizes, int n_in,
                              void* d_out, int out_size)
{
    bool dictOrder = (in_sizes[5] == B_*T_);
    int o = dictOrder ? 1 : 0;
    const float* image    = (const float*)d_in[0];
    const float* vp       = (const float*)d_in[1];
    const float* label    = (const float*)d_in[2];
    const float* topic    = (const float*)d_in[3];
    const float* temp     = (const float*)d_in[4];
    const int*   text     = (const int*)(dictOrder ? d_in[5] : d_in[26]);
    const float* word_emb = (const float*)d_in[5+o];
    const float* fc_v_w   = (const float*)d_in[6+o];
    const float* fc_v_b   = (const float*)d_in[7+o];
    const float* fc_h_w   = (const float*)d_in[8+o];
    const float* fc_h_b   = (const float*)d_in[9+o];
    const float* fc_m_w   = (const float*)d_in[10+o];
    const float* fc_m_b   = (const float*)d_in[11+o];
    const float* w_ih     = (const float*)d_in[12+o];
    const float* w_hh     = (const float*)d_in[13+o];
    const float* b_ih     = (const float*)d_in[14+o];
    const float* b_hh     = (const float*)d_in[15+o];
    const float* fc_w     = (const float*)d_in[16+o];
    const float* fc_b     = (const float*)d_in[17+o];
    const float* fc_hh_w  = (const float*)d_in[18+o];
    const float* fc_hh_b  = (const float*)d_in[19+o];
    const float* fc_s_w   = (const float*)d_in[20+o];
    const float* fc_s_b   = (const float*)d_in[21+o];
    const float* fc_z_w   = (const float*)d_in[22+o];
    const float* fc_z_b   = (const float*)d_in[23+o];
    const float* fc_p_w   = (const float*)d_in[24+o];
    const float* fc_p_b   = (const float*)d_in[25+o];

    float *imean, *xstat, *vbuf, *hallp, *mbuf, *gstat, *embp, *gep, *gates,
          *hsp, *chhp, *logitsp, *Wcp, *bcp, *bihhp, *hhsp, *wpp;
    cudaGetSymbolAddress((void**)&imean,   g_image_mean);
    cudaGetSymbolAddress((void**)&xstat,   g_x_static);
    cudaGetSymbolAddress((void**)&vbuf,    g_v);
    cudaGetSymbolAddress((void**)&hallp,   g_hall);
    cudaGetSymbolAddress((void**)&mbuf,    g_m);
    cudaGetSymbolAddress((void**)&gstat,   g_gates_static);
    cudaGetSymbolAddress((void**)&embp,    g_emb);
    cudaGetSymbolAddress((void**)&gep,     g_ge);
    cudaGetSymbolAddress((void**)&gates,   g_gates);
    cudaGetSymbolAddress((void**)&hsp,     g_hs);
    cudaGetSymbolAddress((void**)&chhp,    g_chh);
    cudaGetSymbolAddress((void**)&logitsp, g_logits);
    cudaGetSymbolAddress((void**)&Wcp,     g_Wc);
    cudaGetSymbolAddress((void**)&bcp,     g_bc);
    cudaGetSymbolAddress((void**)&bihhp,   g_bihh);
    cudaGetSymbolAddress((void**)&hhsp,    g_hhs);
    cudaGetSymbolAddress((void**)&wpp,     g_wp);

    float* out0 = (float*)d_out;
    float* out1 = out0 + (size_t)B_*T_*V_;
    float* out2 = out1 + (size_t)B_*T_*65;

    // 4 streams total: stream 0 = recurrence only; s1/s2/s3 = chains by t%3.
    // Probes the graph-upload-leak boundary (3 clean, 5 leaked 2MB; 4 untested).
    static cudaStream_t sl[3] = {};
    static cudaEvent_t evH = nullptr, evV = nullptr, evD[3] = {};
    if (!sl[0]) {
        for (int i = 0; i < 3; i++) {
            cudaStreamCreateWithFlags(&sl[i], cudaStreamNonBlocking);
            cudaEventCreateWithFlags(&evD[i], cudaEventDisableTiming);
        }
        cudaEventCreateWithFlags(&evH, cudaEventDisableTiming);
        cudaEventCreateWithFlags(&evV, cudaEventDisableTiming);
    }

    SideArgs sa{image, temp, fc_w, fc_b, fc_z_w, fc_z_b, fc_p_b,
                hallp, hsp, hhsp, chhp, logitsp, Wcp, bcp, wpp, out0, out1};

    // ---- prologue: v GEMM on s1 (independent), rest on stream 0 ----
    mma_tf32<<<dim3(E_/128, (B_*P_)/64), 256, 0, sl[0]>>>(image, E_, fc_v_w, E_, fc_v_b,
                                                          nullptr, 1, 0, vbuf, H_,
                                                          B_*P_, H_, E_, 0);
    cudaEventRecord(evV, sl[0]);
    cudaStreamWaitEvent(sl[1], evV, 0);   // other lanes also read g_v
    cudaStreamWaitEvent(sl[2], evV, 0);

    k_round<<<((V_*E_/4) + 255)/256, 256>>>(fc_p_w);
    k_imean<<<(B_*E_ + 255)/256, 256>>>(image);
    k_xstatic<<<(B_*STAT + 255)/256, 256>>>(vp, label, topic);
    k_prep<<<(1024*512 + 255)/256, 256>>>(fc_hh_w, fc_hh_b, fc_s_w, fc_s_b, b_ih, b_hh);
    k_emb<<<(T_*B_*E_ + 255)/256, 256>>>(text, word_emb);
    gemm32k<<<dim3(16, 2), 256>>>(imean, E_, fc_h_w, E_, fc_h_b, nullptr, 0,
                                  hallp, H_, B_, H_, E_, 2, 0, 0);
    gemm32k<<<dim3(16, 2), 256>>>(imean, E_, fc_m_w, E_, fc_m_b, nullptr, 0,
                                  mbuf, H_, B_, H_, E_, 2, 0, 0);
    gemm32k<<<dim3(G4/32, 2), 256>>>(xstat, STAT, w_ih, IN_, bihhp, nullptr, 0,
                                     gstat, G4, B_, G4, STAT, 0, 0, 0);
    mma_tf32<<<dim3(G4/128, (T_*B_)/64), 256>>>(embp, E_, w_ih + STAT, IN_, nullptr,
                                                gstat, 64, G4, gep, G4, T_*B_, G4, E_, 0);

    // ---- stream 0: pure recurrence; sl[t%3]: side chains ----
    for (int t = 0; t < T_; t++) {
        gemm32k<<<dim3(G4/32, 2), 256>>>(hallp + (size_t)t*B_*H_, H_, w_hh, H_,
                                         nullptr, gep + (size_t)t*B_*G4, 0,
                                         gates, G4, B_, G4, H_, 0, 0, 0);
        k_lstm<<<(B_*H_ + 255)/256, 256>>>(t);
        cudaEventRecord(evH, 0);

        int slot = t % 3;
        cudaStreamWaitEvent(sl[slot], evH, 0);
        launch_side(sl[slot], t, slot, sa);
    }
    for (int i = 0; i < 3; i++) {
        cudaEventRecord(evD[i], sl[i]);
        cudaStreamWaitEvent(0, evD[i], 0);
    }
    k_final<<<1, 64>>>(out2);
}

// round 17
// speedup vs baseline: 1.4407x; 1.1209x over previous
#include <cuda_runtime.h>
#include <math.h>
#include <float.h>
#include <stdint.h>

#define B_   64
#define T_   32
#define P_   64
#define E_   512
#define H_   512
#define V_   30000
#define IN_  1568
#define G4   2048      // 4*H
#define STAT 1056      // time-invariant prefix of x
#define NS   3         // side-chain buffer slots (one per side lane)

// ---------------- scratch (static device memory) ----------------
__device__ __align__(16) float g_image_mean[B_*E_];
__device__ __align__(16) float g_x_static[B_*STAT];
__device__ __align__(16) float g_v[B_*P_*H_];
__device__ __align__(16) float g_hall[(T_+1)*B_*H_];   // h(0..T)
__device__ __align__(16) float g_m[2][B_*H_];
__device__ __align__(16) float g_gates_static[B_*G4];
__device__ __align__(16) float g_emb[T_*B_*E_];
__device__ __align__(16) float g_ge[T_*B_*G4];
__device__ __align__(16) float g_gates[B_*G4];
__device__ __align__(16) float g_hs[NS][B_*1024];
__device__ __align__(16) float g_hhs[NS][B_*1024];
__device__ __align__(16) float g_chh[NS][B_*E_];
__device__ __align__(16) float g_logits[NS][B_*V_];
__device__ __align__(16) float g_wp[(size_t)V_*E_];    // fc_p_w pre-rounded to tf32 bits
__device__ __align__(16) float g_Wc[1024*E_];
__device__ __align__(16) float g_bc[1024];
__device__ __align__(16) float g_bihh[G4];
__device__ __align__(16) float g_maxlp[T_*B_];

// ---------------- tf32 mma helpers ----------------
__device__ __forceinline__ unsigned cvt_tf32(float x) {
    unsigned u; asm("cvt.rna.tf32.f32 %0, %1;" : "=r"(u) : "f"(x)); return u;
}
__device__ __forceinline__ void mma8(float* c, unsigned a0, unsigned a1, unsigned a2, unsigned a3,
                                     unsigned b0, unsigned b1) {
    asm volatile("mma.sync.aligned.m16n8k8.row.col.f32.tf32.tf32.f32 "
                 "{%0,%1,%2,%3}, {%4,%5,%6,%7}, {%8,%9}, {%0,%1,%2,%3};"
                 : "+f"(c[0]), "+f"(c[1]), "+f"(c[2]), "+f"(c[3])
                 : "r"(a0), "r"(a1), "r"(a2), "r"(a3), "r"(b0), "r"(b1));
}
__device__ __forceinline__ float tanh_acc(float x) {
    float xc = fminf(fmaxf(x, -10.f), 10.f);
    float e = __expf(2.f * xc);
    return __fdividef(e - 1.f, e + 1.f);
}

// C(MxN) = A(MxK) @ W(NxK)^T + bias + addend[(m%amod)*addN + n]  (single-pass TF32)
// Block tile 64(M) x 128(N), 256 threads = 8 warps as 4(M) x 2(N).
// rawA/rawB != 0: operand already holds tf32-rounded bits -> skip cvt on staging.
// Register-prefetch pipeline: next k-tile's global loads issue before the mma
// phase of the current tile, hiding load latency behind tensor work.
__global__ __launch_bounds__(256)
void mma_tf32(const float* __restrict__ A, int lda,
              const float* __restrict__ W, int ldw,
              const float* __restrict__ bias,
              const float* __restrict__ addend, int amod, int addN,
              float* __restrict__ C, int ldc, int M, int N, int K,
              int rawA, int rawB)
{
    __shared__ float As[64][42];
    __shared__ float Bs[128][42];
    const int tid = threadIdx.x;
    const int m0 = blockIdx.y * 64, n0 = blockIdx.x * 128;
    const int warp = tid >> 5, lane = tid & 31;
    const int wm = warp & 3, wn = warp >> 2;
    const int g = lane >> 2, t = lane & 3;

    // per-thread staging coordinates
    const int rA[2]  = { tid >> 3, (tid + 256) >> 3 };
    const int c4A    = (tid & 7) * 4;
    const int sbA    = (c4A & 24) + ((c4A & 4) ? 1 : 0);

    float c[8][4];
#pragma unroll
    for (int i = 0; i < 8; i++)
#pragma unroll
        for (int j = 0; j < 4; j++) c[i][j] = 0.f;

    float4 regA[2], regB[4];
    // preload tile 0
#pragma unroll
    for (int ii = 0; ii < 2; ii++)
        regA[ii] = *(const float4*)(A + (size_t)(m0 + rA[ii]) * lda + c4A);
#pragma unroll
    for (int ii = 0; ii < 4; ii++) {
        int r = (tid + ii * 256) >> 3;
        int nrow = n0 + r;
        regB[ii] = (nrow < N) ? *(const float4*)(W + (size_t)nrow * ldw + c4A)
                              : make_float4(0.f, 0.f, 0.f, 0.f);
    }

    for (int kc = 0; kc < K; kc += 32) {
        // store staged tile to smem
#pragma unroll
        for (int ii = 0; ii < 2; ii++) {
            float4 va = regA[ii];
            int r = rA[ii];
            if (rawA) {
                As[r][sbA+0] = va.x; As[r][sbA+2] = va.y;
                As[r][sbA+4] = va.z; As[r][sbA+6] = va.w;
            } else {
                As[r][sbA+0] = __uint_as_float(cvt_tf32(va.x));
                As[r][sbA+2] = __uint_as_float(cvt_tf32(va.y));
                As[r][sbA+4] = __uint_as_float(cvt_tf32(va.z));
                As[r][sbA+6] = __uint_as_float(cvt_tf32(va.w));
            }
        }
#pragma unroll
        for (int ii = 0; ii < 4; ii++) {
            float4 vb = regB[ii];
            int r = (tid + ii * 256) >> 3;
            if (rawB) {
                Bs[r][sbA+0] = vb.x; Bs[r][sbA+2] = vb.y;
                Bs[r][sbA+4] = vb.z; Bs[r][sbA+6] = vb.w;
            } else {
                Bs[r][sbA+0] = __uint_as_float(cvt_tf32(vb.x));
                Bs[r][sbA+2] = __uint_as_float(cvt_tf32(vb.y));
                Bs[r][sbA+4] = __uint_as_float(cvt_tf32(vb.z));
                Bs[r][sbA+6] = __uint_as_float(cvt_tf32(vb.w));
            }
        }
        __syncthreads();

        // issue next tile's loads (overlap with mma below)
        int kn = kc + 32;
        if (kn < K) {
#pragma unroll
            for (int ii = 0; ii < 2; ii++)
                regA[ii] = *(const float4*)(A + (size_t)(m0 + rA[ii]) * lda + kn + c4A);
#pragma unroll
            for (int ii = 0; ii < 4; ii++) {
                int r = (tid + ii * 256) >> 3;
                int nrow = n0 + r;
                regB[ii] = (nrow < N) ? *(const float4*)(W + (size_t)nrow * ldw + kn + c4A)
                                      : make_float4(0.f, 0.f, 0.f, 0.f);
            }
        }

#pragma unroll
        for (int j = 0; j < 4; j++) {
            const int ra = wm*16 + g, ca = j*8 + 2*t;
            float2 aLo = *(const float2*)&As[ra][ca];
            float2 aHi = *(const float2*)&As[ra + 8][ca];
            unsigned a0 = __float_as_uint(aLo.x), a1 = __float_as_uint(aHi.x);
            unsigned a2 = __float_as_uint(aLo.y), a3 = __float_as_uint(aHi.y);
#pragma unroll
            for (int nt = 0; nt < 8; nt++) {
                float2 bb = *(const float2*)&Bs[wn*64 + nt*8 + g][ca];
                mma8(c[nt], a0, a1, a2, a3, __float_as_uint(bb.x), __float_as_uint(bb.y));
            }
        }
        __syncthreads();
    }

    const int rm0 = m0 + wm*16 + g, rm1 = rm0 + 8;
#pragma unroll
    for (int nt = 0; nt < 8; nt++) {
        int cn = n0 + wn*64 + nt*8 + 2*t;
#pragma unroll
        for (int q = 0; q < 2; q++) {
            int n = cn + q;
            if (n >= N) continue;
            float bv = bias ? bias[n] : 0.f;
            float x0 = c[nt][q] + bv;
            float x1 = c[nt][2+q] + bv;
            if (addend) {
                x0 += addend[(size_t)(rm0 % amod) * addN + n];
                x1 += addend[(size_t)(rm1 % amod) * addN + n];
            }
            C[(size_t)rm0 * ldc + n] = x0;
            C[(size_t)rm1 * ldc + n] = x1;
        }
    }
}

// ---------------- fp32 32x32-tile GEMM ----------------
__global__ __launch_bounds__(256)
void gemm32k(const float* __restrict__ A, int lda,
             const float* __restrict__ W, int ldw,
             const float* __restrict__ bias,
             const float* __restrict__ addend, int addmod,
             float* __restrict__ C, int ldc,
             int M, int N, int K, int act,
             int asplit_n, int asplit_off)
{
    __shared__ float As[32][36];
    __shared__ float Ws[32][36];
    const int bn0 = blockIdx.x * 32;
    const int bm0 = blockIdx.y * 32;
    if (asplit_off && bn0 >= asplit_n) A += asplit_off;
    const int tid = threadIdx.x;
    const int tx = tid & 15, ty = tid >> 4;
    const int lr = tid >> 3;
    const int lq = (tid & 7) * 4;
    float acc00=0.f, acc01=0.f, acc10=0.f, acc11=0.f;

    const int am = bm0 + lr;
    const int wn = bn0 + lr;
    const float* Ap = A + (size_t)am * lda + lq;
    const float* Wp = W + (size_t)wn * ldw + lq;

    for (int k0 = 0; k0 < K; k0 += 32) {
        float4 va = (am < M) ? __ldg((const float4*)(Ap + k0)) : make_float4(0.f,0.f,0.f,0.f);
        float4 vw = (wn < N) ? __ldg((const float4*)(Wp + k0)) : make_float4(0.f,0.f,0.f,0.f);
        As[lq+0][lr] = va.x; As[lq+1][lr] = va.y; As[lq+2][lr] = va.z; As[lq+3][lr] = va.w;
        Ws[lq+0][lr] = vw.x; Ws[lq+1][lr] = vw.y; Ws[lq+2][lr] = vw.z; Ws[lq+3][lr] = vw.w;
        __syncthreads();
#pragma unroll
        for (int k = 0; k < 32; k++) {
            float2 a2 = *(const float2*)&As[k][ty*2];
            float2 b2 = *(const float2*)&Ws[k][tx*2];
            acc00 += a2.x * b2.x; acc01 += a2.x * b2.y;
            acc10 += a2.y * b2.x; acc11 += a2.y * b2.y;
        }
        __syncthreads();
    }
    float accs[2][2] = {{acc00, acc01},{acc10, acc11}};
#pragma unroll
    for (int i = 0; i < 2; i++) {
        int m = bm0 + ty*2 + i;
        if (m >= M) continue;
#pragma unroll
        for (int j = 0; j < 2; j++) {
            int n = bn0 + tx*2 + j;
            if (n >= N) continue;
            float x = accs[i][j];
            if (bias)   x += bias[n];
            if (addend) x += addend[(size_t)(addmod ? (m % addmod) : m) * N + n];
            if (act == 1)      x = fmaxf(x, 0.f);
            else if (act == 2) x = tanhf(x);
            C[(size_t)m * ldc + n] = x;
        }
    }
}

// ---------------- small kernels ----------------
__global__ void k_imean(const float* __restrict__ image)
{
    int i = blockIdx.x * blockDim.x + threadIdx.x;
    if (i >= B_*E_) return;
    int b = i >> 9, e = i & 511;
    const float* p = image + (size_t)b * P_ * E_ + e;
    float s = 0.f;
#pragma unroll 8
    for (int pp = 0; pp < P_; pp++) s += p[(size_t)pp * E_];
    g_image_mean[i] = s * (1.f / P_);
}

__global__ void k_xstatic(const float* __restrict__ vp, const float* __restrict__ lab,
                          const float* __restrict__ topic)
{
    int i = blockIdx.x * blockDim.x + threadIdx.x;
    if (i >= B_*STAT) return;
    int b = i / STAT, c = i % STAT;
    float val;
    if (c < 512)        val = g_image_mean[b*512 + c];
    else if (c < 528)   val = vp[b*16 + c - 512];
    else if (c < 544)   val = lab[b*16 + c - 528];
    else                val = topic[b*512 + c - 544];
    g_x_static[i] = val;
}

__global__ void k_prep(const float* __restrict__ fhh_w, const float* __restrict__ fhh_b,
                       const float* __restrict__ fs_w,  const float* __restrict__ fs_b,
                       const float* __restrict__ bih,   const float* __restrict__ bhh)
{
    int i = blockIdx.x * blockDim.x + threadIdx.x;
    if (i < 1024*512)
        g_Wc[i] = (i < 512*512) ? fhh_w[i] : fs_w[i - 512*512];
    if (i < 1024)
        g_bc[i] = (i < 512) ? fhh_b[i] : fs_b[i - 512];
    if (i < 2048)
        g_bihh[i] = bih[i] + bhh[i];
}

// pre-round fc_p_w to tf32 bits (vectorized)
__global__ void k_round(const float* __restrict__ w)
{
    size_t i = (size_t)(blockIdx.x * blockDim.x + threadIdx.x) * 4;
    if (i >= (size_t)V_*E_) return;
    float4 v = *(const float4*)(w + i);
    float4 r;
    r.x = __uint_as_float(cvt_tf32(v.x));
    r.y = __uint_as_float(cvt_tf32(v.y));
    r.z = __uint_as_float(cvt_tf32(v.z));
    r.w = __uint_as_float(cvt_tf32(v.w));
    *(float4*)(g_wp + i) = r;
}

__global__ void k_emb(const int* __restrict__ text, const float* __restrict__ wemb)
{
    int i = blockIdx.x * blockDim.x + threadIdx.x;
    if (i >= T_*B_*E_) return;
    int e = i & 511;
    int r = i >> 9;
    int b = r & 63, t = r >> 6;
    int tok = (t == 0) ? 0 : text[b*T_ + (t-1)];
    g_emb[i] = wemb[(size_t)tok * E_ + e];
}

// LSTM pointwise
__global__ void k_lstm(int t)
{
    int i = blockIdx.x * blockDim.x + threadIdx.x;
    if (i >= B_*H_) return;
    int b = i >> 9, h = i & 511;
    const float* g = g_gates + (size_t)b * G4;
    float ig = 1.f / (1.f + expf(-g[h]));
    float fg = 1.f / (1.f + expf(-g[h + 512]));
    float gg = tanhf(g[h + 1024]);
    float og = 1.f / (1.f + expf(-g[h + 1536]));
    float mn = fg * g_m[t & 1][i] + ig * gg;
    float hn = og * tanhf(mn);
    g_m[(t + 1) & 1][i] = mn;
    g_hall[(size_t)(t + 1) * B_ * H_ + i] = hn;
}

// FUSED attention: z + softmax + context + chh, one block per batch.
// chh is stored tf32-pre-rounded (identical value to what the vocab GEMM's
// internal cvt would produce -> numerics unchanged, enables rawA staging).
__global__ __launch_bounds__(256)
void k_attn(const float* __restrict__ image,
            const float* __restrict__ fz_w, const float* __restrict__ fz_b,
            float* __restrict__ out_attn, int t, int slot)
{
    int b = blockIdx.x;
    __shared__ float hhsm[512];
    __shared__ float wz[512];
    __shared__ float zs[65];
    __shared__ float as_[65];
    int tid = threadIdx.x;
    int warp = tid >> 5, lane = tid & 31;
    const float* hhs = g_hhs[slot];
    for (int h = tid; h < 512; h += 256) { hhsm[h] = hhs[b*1024 + h]; wz[h] = fz_w[h]; }
    __syncthreads();
    for (int p = warp; p < 65; p += 8) {
        const float* src = (p < 64) ? (g_v + ((size_t)b*64 + p) * 512)
                                    : (hhs + b*1024 + 512);
        float s = 0.f;
        for (int h = lane; h < 512; h += 32) s += tanh_acc(src[h] + hhsm[h]) * wz[h];
#pragma unroll
        for (int o = 16; o; o >>= 1) s += __shfl_xor_sync(0xffffffffu, s, o);
        if (!lane) zs[p] = s + fz_b[0];
    }
    __syncthreads();
    if (warp == 0) {
        float z0 = zs[lane];
        float z1 = (lane + 32 < 64) ? zs[lane + 32] : -FLT_MAX;
        float z2 = (lane == 0) ? zs[64] : -FLT_MAX;
        float mx = fmaxf(fmaxf(z0, z1), z2);
#pragma unroll
        for (int o = 16; o; o >>= 1) mx = fmaxf(mx, __shfl_xor_sync(0xffffffffu, mx, o));
        float e0 = expf(z0 - mx);
        float e1 = (lane + 32 < 64) ? expf(z1 - mx) : 0.f;
        float e2 = (lane == 0) ? expf(z2 - mx) : 0.f;
        float se = e0 + e1 + e2;
#pragma unroll
        for (int o = 16; o; o >>= 1) se += __shfl_xor_sync(0xffffffffu, se, o);
        float inv = 1.f / se;
        float* oat = out_attn + ((size_t)b*T_ + t)*65;
        as_[lane] = e0 * inv;  oat[lane] = e0 * inv;
        if (lane + 32 < 64) { as_[lane+32] = e1 * inv; oat[lane+32] = e1 * inv; }
        if (lane == 0)      { as_[64]     = e2 * inv; oat[64]      = e2 * inv; }
    }
    __syncthreads();
    const float* srow = g_hs[slot] + b*1024 + 512;
    const float* hh   = g_hs[slot] + b*1024;
    float* chh = g_chh[slot] + b*512;
    for (int e = tid; e < 512; e += 256) {
        float c = as_[64] * srow[e];
        const float* im = image + (size_t)b * P_ * E_ + e;
#pragma unroll 8
        for (int p = 0; p < 64; p++) c += as_[p] * im[(size_t)p * E_];
        chh[e] = __uint_as_float(cvt_tf32(c + hh[e]));   // pre-rounded for rawA
    }
}

// FUSED log-softmax: one block per batch, 1024 threads, two in-kernel passes.
__global__ __launch_bounds__(1024)
void k_lsm(const float* __restrict__ temp, float* __restrict__ out0, int t, int slot)
{
    int b = blockIdx.x, tid = threadIdx.x;
    int warp = tid >> 5, lane = tid & 31;
    __shared__ float rm[32], rs[32];
    __shared__ float bM, bS;
    const float it = 1.f / temp[b];
    const float4* x4 = (const float4*)(g_logits[slot] + (size_t)b * V_);

    float m = -FLT_MAX, s = 0.f;
    for (int i = tid; i < 7500; i += 1024) {
        float4 v = x4[i];
        float a = v.x*it, bb = v.y*it, cc = v.z*it, d = v.w*it;
        m = fmaxf(fmaxf(m, fmaxf(a, bb)), fmaxf(cc, d));
        s += __expf(a) + __expf(bb) + __expf(cc) + __expf(d);
    }
#pragma unroll
    for (int o = 16; o; o >>= 1) {
        m = fmaxf(m, __shfl_xor_sync(0xffffffffu, m, o));
        s += __shfl_xor_sync(0xffffffffu, s, o);
    }
    if (!lane) { rm[warp] = m; rs[warp] = s; }
    __syncthreads();
    if (warp == 0) {
        float M2 = rm[lane], S2 = rs[lane];
#pragma unroll
        for (int o = 16; o; o >>= 1) {
            M2 = fmaxf(M2, __shfl_xor_sync(0xffffffffu, M2, o));
            S2 += __shfl_xor_sync(0xffffffffu, S2, o);
        }
        if (!lane) { bM = M2; bS = S2; }
    }
    __syncthreads();
    float logS = __logf(bS);
    float4* o4 = (float4*)(out0 + ((size_t)b*T_ + t)*V_);
    for (int i = tid; i < 7500; i += 1024) {
        float4 v = x4[i];
        o4[i] = make_float4(v.x*it - logS, v.y*it - logS, v.z*it - logS, v.w*it - logS);
    }
    if (tid == 0) g_maxlp[t*64 + b] = bM - logS;
}

__global__ void k_final(float* __restrict__ out2)
{
    int b = threadIdx.x;
    if (b >= B_) return;
    float s = 0.f;
    for (int t = 0; t < T_; t++) s += g_maxlp[t*64 + b];
    out2[b] = s;
}

// ---------------- host ----------------
struct SideArgs {
    const float* image; const float* temp;
    const float* fc_w; const float* fc_b;
    const float* fc_z_w; const float* fc_z_b;
    const float* fc_p_b;
    float *hallp, *hsp, *hhsp, *chhp, *logitsp, *Wcp, *bcp, *wpp;
    float *out0, *out1;
};

static void launch_side(cudaStream_t ss, int t, int slot, const SideArgs& a)
{
    gemm32k<<<dim3(1024/32, 2), 256, 0, ss>>>(a.hallp + (size_t)(t+1)*B_*H_, H_, a.fc_w, H_,
                                              a.fc_b, nullptr, 0,
                                              a.hsp + (size_t)slot*B_*1024, 1024,
                                              B_, 1024, H_, 1, 0, 0);
    gemm32k<<<dim3(1024/32, 2), 256, 0, ss>>>(a.hsp + (size_t)slot*B_*1024, 1024, a.Wcp, H_,
                                              a.bcp, nullptr, 0,
                                              a.hhsp + (size_t)slot*B_*1024, 1024,
                                              B_, 1024, H_, 0, 512, 512);
    k_attn<<<B_, 256, 0, ss>>>(a.image, a.fc_z_w, a.fc_z_b, a.out1, t, slot);
    mma_tf32<<<dim3((V_ + 127)/128, 1), 256, 0, ss>>>(a.chhp + (size_t)slot*B_*E_, E_,
                                                      a.wpp, E_, a.fc_p_b, nullptr, 1, 0,
                                                      a.logitsp + (size_t)slot*B_*V_, V_,
                                                      B_, V_, E_, 1 /*rawA*/, 1 /*rawB*/);
    k_lsm<<<B_, 1024, 0, ss>>>(a.temp, a.out0, t, slot);
}

extern "C" void kernel_launch(void* const* d_in, const int* in_sizes, int n_in,
                              void* d_out, int out_size)
{
    bool dictOrder = (in_sizes[5] == B_*T_);
    int o = dictOrder ? 1 : 0;
    const float* image    = (const float*)d_in[0];
    const float* vp       = (const float*)d_in[1];
    const float* label    = (const float*)d_in[2];
    const float* topic    = (const float*)d_in[3];
    const float* temp     = (const float*)d_in[4];
    const int*   text     = (const int*)(dictOrder ? d_in[5] : d_in[26]);
    const float* word_emb = (const float*)d_in[5+o];
    const float* fc_v_w   = (const float*)d_in[6+o];
    const float* fc_v_b   = (const float*)d_in[7+o];
    const float* fc_h_w   = (const float*)d_in[8+o];
    const float* fc_h_b   = (const float*)d_in[9+o];
    const float* fc_m_w   = (const float*)d_in[10+o];
    const float* fc_m_b   = (const float*)d_in[11+o];
    const float* w_ih     = (const float*)d_in[12+o];
    const float* w_hh     = (const float*)d_in[13+o];
    const float* b_ih     = (const float*)d_in[14+o];
    const float* b_hh     = (const float*)d_in[15+o];
    const float* fc_w     = (const float*)d_in[16+o];
    const float* fc_b     = (const float*)d_in[17+o];
    const float* fc_hh_w  = (const float*)d_in[18+o];
    const float* fc_hh_b  = (const float*)d_in[19+o];
    const float* fc_s_w   = (const float*)d_in[20+o];
    const float* fc_s_b   = (const float*)d_in[21+o];
    const float* fc_z_w   = (const float*)d_in[22+o];
    const float* fc_z_b   = (const float*)d_in[23+o];
    const float* fc_p_w   = (const float*)d_in[24+o];
    const float* fc_p_b   = (const float*)d_in[25+o];

    float *imean, *xstat, *vbuf, *hallp, *mbuf, *gstat, *embp, *gep, *gates,
          *hsp, *chhp, *logitsp, *Wcp, *bcp, *bihhp, *hhsp, *wpp;
    cudaGetSymbolAddress((void**)&imean,   g_image_mean);
    cudaGetSymbolAddress((void**)&xstat,   g_x_static);
    cudaGetSymbolAddress((void**)&vbuf,    g_v);
    cudaGetSymbolAddress((void**)&hallp,   g_hall);
    cudaGetSymbolAddress((void**)&mbuf,    g_m);
    cudaGetSymbolAddress((void**)&gstat,   g_gates_static);
    cudaGetSymbolAddress((void**)&embp,    g_emb);
    cudaGetSymbolAddress((void**)&gep,     g_ge);
    cudaGetSymbolAddress((void**)&gates,   g_gates);
    cudaGetSymbolAddress((void**)&hsp,     g_hs);
    cudaGetSymbolAddress((void**)&chhp,    g_chh);
    cudaGetSymbolAddress((void**)&logitsp, g_logits);
    cudaGetSymbolAddress((void**)&Wcp,     g_Wc);
    cudaGetSymbolAddress((void**)&bcp,     g_bc);
    cudaGetSymbolAddress((void**)&bihhp,   g_bihh);
    cudaGetSymbolAddress((void**)&hhsp,    g_hhs);
    cudaGetSymbolAddress((void**)&wpp,     g_wp);

    float* out0 = (float*)d_out;
    float* out1 = out0 + (size_t)B_*T_*V_;
    float* out2 = out1 + (size_t)B_*T_*65;

    // 4 streams total (R16-proven leak-free; 5 leaked).
    static cudaStream_t sl[3] = {};
    static cudaEvent_t evH = nullptr, evV = nullptr, evD[3] = {};
    if (!sl[0]) {
        for (int i = 0; i < 3; i++) {
            cudaStreamCreateWithFlags(&sl[i], cudaStreamNonBlocking);
            cudaEventCreateWithFlags(&evD[i], cudaEventDisableTiming);
        }
        cudaEventCreateWithFlags(&evH, cudaEventDisableTiming);
        cudaEventCreateWithFlags(&evV, cudaEventDisableTiming);
    }

    SideArgs sa{image, temp, fc_w, fc_b, fc_z_w, fc_z_b, fc_p_b,
                hallp, hsp, hhsp, chhp, logitsp, Wcp, bcp, wpp, out0, out1};

    // ---- prologue: v GEMM on sl[0] (independent), rest on stream 0 ----
    mma_tf32<<<dim3(E_/128, (B_*P_)/64), 256, 0, sl[0]>>>(image, E_, fc_v_w, E_, fc_v_b,
                                                          nullptr, 1, 0, vbuf, H_,
                                                          B_*P_, H_, E_, 0, 0);
    cudaEventRecord(evV, sl[0]);
    cudaStreamWaitEvent(sl[1], evV, 0);
    cudaStreamWaitEvent(sl[2], evV, 0);

    k_round<<<((V_*E_/4) + 255)/256, 256>>>(fc_p_w);
    k_imean<<<(B_*E_ + 255)/256, 256>>>(image);
    k_xstatic<<<(B_*STAT + 255)/256, 256>>>(vp, label, topic);
    k_prep<<<(1024*512 + 255)/256, 256>>>(fc_hh_w, fc_hh_b, fc_s_w, fc_s_b, b_ih, b_hh);
    k_emb<<<(T_*B_*E_ + 255)/256, 256>>>(text, word_emb);
    gemm32k<<<dim3(16, 2), 256>>>(imean, E_, fc_h_w, E_, fc_h_b, nullptr, 0,
                                  hallp, H_, B_, H_, E_, 2, 0, 0);
    gemm32k<<<dim3(16, 2), 256>>>(imean, E_, fc_m_w, E_, fc_m_b, nullptr, 0,
                                  mbuf, H_, B_, H_, E_, 2, 0, 0);
    gemm32k<<<dim3(G4/32, 2), 256>>>(xstat, STAT, w_ih, IN_, bihhp, nullptr, 0,
                                     gstat, G4, B_, G4, STAT, 0, 0, 0);
    mma_tf32<<<dim3(G4/128, (T_*B_)/64), 256>>>(embp, E_, w_ih + STAT, IN_, nullptr,
                                                gstat, 64, G4, gep, G4, T_*B_, G4, E_, 0, 0);

    // ---- stream 0: pure recurrence; sl[t%3]: side chains ----
    for (int t = 0; t < T_; t++) {
        gemm32k<<<dim3(G4/32, 2), 256>>>(hallp + (size_t)t*B_*H_, H_, w_hh, H_,
                                         nullptr, gep + (size_t)t*B_*G4, 0,
                                         gates, G4, B_, G4, H_, 0, 0, 0);
        k_lstm<<<(B_*H_ + 255)/256, 256>>>(t);
        cudaEventRecord(evH, 0);

        int slot = t % 3;
        cudaStreamWaitEvent(sl[slot], evH, 0);
        launch_side(sl[slot], t, slot, sa);
    }
    for (int i = 0; i < 3; i++) {
        cudaEventRecord(evD[i], sl[i]);
        cudaStreamWaitEvent(0, evD[i], 0);
    }
    k_final<<<1, 64>>>(out2);
}